// round 9
// baseline (speedup 1.0000x reference)
#include <cuda_runtime.h>
#include <mma.h>

using namespace nvcuda;

#define NRW 65536
#define HD  256
#define LDK 260
#define LDH 260

// ---------------- static device buffers --------------------------------------
__device__ __align__(256) float g_Xp[NRW * 32];             // padded input (cols 20..31 = 0)
__device__ __align__(256) float g_Wih0[1024 * 32];          // padded W_ih_00
__device__ __align__(256) float g_biasRep[4][16 * 1024];    // 16 replicated rows of (b_ih+b_hh)
__device__ __align__(256) float g_Ga[(size_t)NRW * 1024];   // gate preacts ping
__device__ __align__(256) float g_Gb[(size_t)NRW * 1024];   // gate preacts pong
__device__ __align__(256) float g_Ybuf[3][(size_t)NRW * HD];

typedef wmma::fragment<wmma::matrix_a, 16, 16, 8, wmma::precision::tf32, wmma::row_major> FragA;
typedef wmma::fragment<wmma::matrix_b, 16, 16, 8, wmma::precision::tf32, wmma::col_major> FragB;
typedef wmma::fragment<wmma::accumulator, 16, 16, 8, float> FragC;

__device__ __forceinline__ float sigf(float x) { return 1.0f / (1.0f + __expf(-x)); }

__device__ __forceinline__ void splitA(FragA& h, FragA& l) {
#pragma unroll
    for (int i = 0; i < h.num_elements; i++) {
        float v = h.x[i];
        float hh = wmma::__float_to_tf32(v);
        l.x[i] = wmma::__float_to_tf32(v - hh);
        h.x[i] = hh;
    }
}
__device__ __forceinline__ void splitB(FragB& h, FragB& l) {
#pragma unroll
    for (int i = 0; i < h.num_elements; i++) {
        float v = h.x[i];
        float hh = wmma::__float_to_tf32(v);
        l.x[i] = wmma::__float_to_tf32(v - hh);
        h.x[i] = hh;
    }
}

// 3xTF32 K-loop (head kernel only)
__device__ __forceinline__ void kloop3(FragC& acc, const float* __restrict__ A, int lda,
                                       const float* __restrict__ B, int ldb, int K) {
    for (int k = 0; k < K; k += 8) {
        FragA ah, al;
        FragB bh, bl;
        wmma::load_matrix_sync(ah, A + k, lda);
        wmma::load_matrix_sync(bh, B + k, ldb);
        splitA(ah, al);
        splitB(bh, bl);
        wmma::mma_sync(acc, ah, bh, acc);
        wmma::mma_sync(acc, ah, bl, acc);
        wmma::mma_sync(acc, al, bh, acc);
    }
}

__device__ __forceinline__ unsigned crank() {
    unsigned r;
    asm("mov.u32 %0, %%cluster_ctarank;" : "=r"(r));
    return r;
}
__device__ __forceinline__ float* peer_ptr(float* p, unsigned r) {
    unsigned long long q;
    asm("mapa.u64 %0, %1, %2;" : "=l"(q) : "l"((unsigned long long)p), "r"(r));
    return (float*)q;
}
#define CARR()  asm volatile("barrier.cluster.arrive.aligned;" ::: "memory")
#define CWAIT() asm volatile("barrier.cluster.wait.aligned;" ::: "memory")

// ---------------- prep: pad X / W_ih_00, replicated bias rows ----------------
__global__ void k_prep(const float* __restrict__ x, const float* __restrict__ wih0,
                       const float* __restrict__ bi0, const float* __restrict__ bh0,
                       const float* __restrict__ bi1, const float* __restrict__ bh1,
                       const float* __restrict__ bi2, const float* __restrict__ bh2,
                       const float* __restrict__ bi3, const float* __restrict__ bh3) {
    int tid = blockIdx.x * blockDim.x + threadIdx.x;
    int nt = gridDim.x * blockDim.x;
    for (int i = tid; i < NRW * 20; i += nt)
        g_Xp[(size_t)(i / 20) * 32 + (i % 20)] = x[i];
    for (int i = tid; i < 1024 * 20; i += nt)
        g_Wih0[(i / 20) * 32 + (i % 20)] = wih0[i];
    for (int i = tid; i < 16 * 1024; i += nt) {
        int c = i % 1024;
        g_biasRep[0][i] = bi0[c] + bh0[c];
        g_biasRep[1][i] = bi1[c] + bh1[c];
        g_biasRep[2][i] = bi2[c] + bh2[c];
        g_biasRep[3][i] = bi3[c] + bh3[c];
    }
}

__global__ void k_pad() {}

// ---------------- bulk input projection (layer 0 only, K=32) -----------------
template <int K>
__global__ void __launch_bounds__(256, 1)
bulk_k(const float* __restrict__ X, const float* __restrict__ W,
       const float* __restrict__ bR, float* __restrict__ G) {
    __shared__ float sA[128 * 40];
    __shared__ float sB[128 * 40];
    const int n0 = blockIdx.x * 128;
    const size_t m0 = (size_t)blockIdx.y * 128;
    const int w = threadIdx.x >> 5;
    const int wr = (w >> 1) * 32;
    const int wc = (w & 1) * 64;

    FragC acc[2][4];
#pragma unroll
    for (int a = 0; a < 2; a++)
#pragma unroll
        for (int b = 0; b < 4; b++) wmma::fill_fragment(acc[a][b], 0.0f);

    for (int k0 = 0; k0 < K; k0 += 32) {
        __syncthreads();
        for (int i = threadIdx.x; i < 128 * 32; i += 256) {
            int r = i >> 5, ci = i & 31;
            sA[r * 40 + ci] = X[(m0 + r) * K + k0 + ci];
            sB[r * 40 + ci] = wmma::__float_to_tf32(W[(size_t)(n0 + r) * K + k0 + ci]);
        }
        __syncthreads();
#pragma unroll
        for (int kk = 0; kk < 32; kk += 8) {
            FragA ah[2], al[2];
#pragma unroll
            for (int a = 0; a < 2; a++) {
                wmma::load_matrix_sync(ah[a], &sA[(wr + a * 16) * 40 + kk], 40);
                splitA(ah[a], al[a]);
            }
#pragma unroll
            for (int b = 0; b < 4; b++) {
                FragB bh;
                wmma::load_matrix_sync(bh, &sB[(wc + b * 16) * 40 + kk], 40);
#pragma unroll
                for (int a = 0; a < 2; a++) {
                    wmma::mma_sync(acc[a][b], ah[a], bh, acc[a][b]);
                    wmma::mma_sync(acc[a][b], al[a], bh, acc[a][b]);
                }
            }
        }
    }
#pragma unroll
    for (int b = 0; b < 4; b++) {
        FragC bf;
        wmma::load_matrix_sync(bf, bR + n0 + wc + b * 16, 1024, wmma::mem_row_major);
#pragma unroll
        for (int a = 0; a < 2; a++) {
#pragma unroll
            for (int i = 0; i < bf.num_elements; i++) acc[a][b].x[i] += bf.x[i];
            wmma::store_matrix_sync(G + (m0 + wr + a * 16) * 1024 + n0 + wc + b * 16,
                                    acc[a][b], 1024, wmma::mem_row_major);
        }
    }
}

// ---------------- fused-epilogue: G_next tile for step tprev ------------------
// Warp w of CTA cg computes G_next[rows(tprev), cg*128 + w*16 .. +16).
// A = Y rows (global, L2-hot, just written), B = Wih_next rows (global, L2-hot).
template <int TM, int BEFF>
__device__ __forceinline__ void epilogue(int tprev, int m0, int cg, int w,
                                         const float* __restrict__ Y,
                                         const float* __restrict__ Wn,
                                         const float* __restrict__ bRn,
                                         float* __restrict__ Gn) {
    constexpr int RT = TM / 16;
    const int gc = cg * 128 + w * 16;
    const size_t r0 = (size_t)tprev * BEFF + m0;
    FragC eacc[RT];
#pragma unroll
    for (int i = 0; i < RT; i++)
        wmma::load_matrix_sync(eacc[i], bRn + gc, 1024, wmma::mem_row_major);
#pragma unroll 4
    for (int k = 0; k < HD; k += 8) {
        FragB bh;
        wmma::load_matrix_sync(bh, Wn + (size_t)gc * HD + k, HD);
#pragma unroll
        for (int i = 0; i < bh.num_elements; i++)
            bh.x[i] = wmma::__float_to_tf32(bh.x[i]);
#pragma unroll
        for (int i = 0; i < RT; i++) {
            FragA ah, al;
            wmma::load_matrix_sync(ah, Y + (r0 + i * 16) * HD + k, HD);
            splitA(ah, al);
            wmma::mma_sync(eacc[i], ah, bh, eacc[i]);
            wmma::mma_sync(eacc[i], al, bh, eacc[i]);
        }
    }
#pragma unroll
    for (int i = 0; i < RT; i++)
        wmma::store_matrix_sync(Gn + (r0 + i * 16) * 1024 + gc, eacc[i],
                                1024, wmma::mem_row_major);
}

// ---------------- clustered sequential LSTM + fused next-layer projection ----
template <int STEPS, int BEFF, int TM, int DB, bool EPI>
__global__ void __launch_bounds__(256, 1) __cluster_dims__(8, 1, 1)
cseq_k(const float* __restrict__ Whh, const float* __restrict__ G,
       float* __restrict__ Y,
       const float* __restrict__ Wn, const float* __restrict__ bRn,
       float* __restrict__ Gn) {
    extern __shared__ float smem[];
    float* sW = smem;                    // [128][LDK] tf32-rounded Whh slice
    float* sH = smem + 128 * LDK;        // [DB][TM][LDH] replicated h

    const unsigned cg = crank();         // 0..7
    const int rm = blockIdx.x >> 3;      // chain id
    const int m0 = rm * TM;
    const int w = threadIdx.x >> 5;
    const int rt = w >> 1;               // row tile
    const int ck = w & 1;                // 16-col chunk within 32
    const bool act = rt < TM / 16;
    const int jc = (int)cg * 32 + ck * 16;

    // stage Whh slice, pre-rounded to tf32
    for (int idx = threadIdx.x; idx < 128 * 64; idx += 256) {
        const int r = idx >> 6;
        const int k4 = idx & 63;
        const int gate = r >> 5;
        const int hl = r & 31;
        float4 v = *(const float4*)(Whh + (size_t)(gate * 256 + cg * 32 + hl) * 256 + k4 * 4);
        v.x = wmma::__float_to_tf32(v.x);
        v.y = wmma::__float_to_tf32(v.y);
        v.z = wmma::__float_to_tf32(v.z);
        v.w = wmma::__float_to_tf32(v.w);
        *(float4*)(sW + r * LDK + k4 * 4) = v;
    }
    __syncthreads();

    float c8[8];
#pragma unroll
    for (int e = 0; e < 8; e++) c8[e] = 0.0f;

    FragC acc[4];
    if (act) {
#pragma unroll
        for (int g = 0; g < 4; g++)
            wmma::load_matrix_sync(acc[g], G + (size_t)(m0 + rt * 16) * 1024 + g * 256 + jc,
                                   1024, wmma::mem_row_major);
    }

    for (int t = 0; t < STEPS; t++) {
        const size_t base = (size_t)t * BEFF + m0;

        if (t) {
            CWAIT();   // publishes step t-1: peer h in sH + all Y stores
            // fused next-layer projection for step t-1 (independent; all warps)
            if (EPI) epilogue<TM, BEFF>(t - 1, m0, (int)cg, w, Y, Wn, bRn, Gn);

            if (act) {
                const float* hb = sH + (DB == 2 ? ((t & 1) ^ 1) * TM * LDH : 0) + rt * 16 * LDH;
#pragma unroll 4
                for (int k0 = 0; k0 < HD; k0 += 8) {
                    FragA ah, al;
                    wmma::load_matrix_sync(ah, hb + k0, LDH);
                    splitA(ah, al);
#pragma unroll
                    for (int g = 0; g < 4; g++) {
                        FragB bh;
                        wmma::load_matrix_sync(bh, sW + (g * 32 + ck * 16) * LDK + k0, LDK);
                        wmma::mma_sync(acc[g], ah, bh, acc[g]);
                        wmma::mma_sync(acc[g], al, bh, acc[g]);
                    }
                }
            }
        }

        // elementwise in registers; acc[0] becomes h
        if (act) {
#pragma unroll
            for (int e = 0; e < 8; e++) {
                const float pi = acc[0].x[e];
                const float pf = acc[1].x[e];
                const float pg = acc[2].x[e];
                const float po = acc[3].x[e];
                const float cn = sigf(pf) * c8[e] + sigf(pi) * tanhf(pg);
                c8[e] = cn;
                acc[0].x[e] = sigf(po) * tanhf(cn);
            }
            // h -> global Y (covered by the CARR release below)
            wmma::store_matrix_sync(Y + (base + rt * 16) * HD + jc, acc[0], HD,
                                    wmma::mem_row_major);
        }

        if (t + 1 < STEPS) {
            if (DB == 1) { CARR(); CWAIT(); }   // all peers done reading sH
            float* sHw = sH + (DB == 2 ? (t & 1) * TM * LDH : 0)
                       + rt * 16 * LDH + (int)cg * 32 + ck * 16;
            if (act) {
                // store own h fragment directly into every CTA's sH (incl. own)
#pragma unroll
                for (unsigned r = 0; r < 8; r++)
                    wmma::store_matrix_sync(peer_ptr(sHw, r), acc[0], LDH,
                                            wmma::mem_row_major);
            }
            CARR();   // release: DSMEM + global stores visible after peers' CWAIT

            // prefetch next step's G while the barrier drains
            if (act) {
                const size_t base2 = (size_t)(t + 1) * BEFF + m0;
#pragma unroll
                for (int g = 0; g < 4; g++)
                    wmma::load_matrix_sync(acc[g], G + (base2 + rt * 16) * 1024 + g * 256 + jc,
                                           1024, wmma::mem_row_major);
            }
        }
    }

    if (EPI) {  // final step's projection (needs all CTAs' last Y stores)
        CARR();
        CWAIT();
        epilogue<TM, BEFF>(STEPS - 1, m0, (int)cg, w, Y, Wn, bRn, Gn);
    }
}

// ---------------- head: out = tanh((Y2+Y1) @ mlp_w^T + b) @ ad_w^T + ad_b ----
__global__ void __launch_bounds__(256, 2)
head_k(const float* __restrict__ Y2, const float* __restrict__ Y1,
       const float* __restrict__ mlpw, const float* __restrict__ mlpb,
       const float* __restrict__ adw, const float* __restrict__ adb,
       float* __restrict__ out) {
    __shared__ float sx[16][256];
    __shared__ float sh[16][256];
    __shared__ float so[16][48];

    const int warp = threadIdx.x >> 5;
    const size_t m0 = (size_t)blockIdx.x * 16;

    for (int e = threadIdx.x; e < 16 * 256; e += 256) {
        const size_t gi = m0 * 256 + e;
        sx[e / 256][e % 256] = Y2[gi] + Y1[gi];
    }
    __syncthreads();

    for (int st = warp; st < 16; st += 8) {
        FragC acc;
        wmma::fill_fragment(acc, 0.0f);
        kloop3(acc, &sx[0][0], 256, mlpw + (size_t)(st * 16) * 256, 256, 256);
        wmma::store_matrix_sync(&sh[0][st * 16], acc, 256, wmma::mem_row_major);
    }
    __syncthreads();
    for (int e = threadIdx.x; e < 16 * 256; e += 256)
        sh[e / 256][e % 256] = tanhf(sh[e / 256][e % 256] + mlpb[e % 256]);
    __syncthreads();

    if (warp < 3) {
        FragC acc;
        wmma::fill_fragment(acc, 0.0f);
        kloop3(acc, &sh[0][0], 256, adw + (size_t)(warp * 16) * 256, 256, 256);
        wmma::store_matrix_sync(&so[0][warp * 16], acc, 48, wmma::mem_row_major);
    }
    __syncthreads();
    for (int e = threadIdx.x; e < 16 * 48; e += 256)
        out[m0 * 48 + e] = so[e / 48][e % 48] + adb[e % 48];
}

// ---------------- host -------------------------------------------------------
extern "C" void kernel_launch(void* const* d_in, const int* in_sizes, int n_in,
                              void* d_out, int out_size) {
    const float* X     = (const float*)d_in[0];
    const float* Wih00 = (const float*)d_in[1];
    const float* Whh00 = (const float*)d_in[2];
    const float* bih00 = (const float*)d_in[3];
    const float* bhh00 = (const float*)d_in[4];
    const float* Wih01 = (const float*)d_in[5];
    const float* Whh01 = (const float*)d_in[6];
    const float* bih01 = (const float*)d_in[7];
    const float* bhh01 = (const float*)d_in[8];
    const float* Wih10 = (const float*)d_in[9];
    const float* Whh10 = (const float*)d_in[10];
    const float* bih10 = (const float*)d_in[11];
    const float* bhh10 = (const float*)d_in[12];
    const float* Wih11 = (const float*)d_in[13];
    const float* Whh11 = (const float*)d_in[14];
    const float* bih11 = (const float*)d_in[15];
    const float* bhh11 = (const float*)d_in[16];
    const float* mlpw  = (const float*)d_in[17];
    const float* mlpb  = (const float*)d_in[18];
    const float* adw   = (const float*)d_in[19];
    const float* adb   = (const float*)d_in[20];
    float* out = (float*)d_out;

    float *Xp, *Wih0p, *bRp, *G0, *G1, *Yb;
    cudaGetSymbolAddress((void**)&Xp, g_Xp);
    cudaGetSymbolAddress((void**)&Wih0p, g_Wih0);
    cudaGetSymbolAddress((void**)&bRp, g_biasRep);
    cudaGetSymbolAddress((void**)&G0, g_Ga);
    cudaGetSymbolAddress((void**)&G1, g_Gb);
    cudaGetSymbolAddress((void**)&Yb, g_Ybuf);
    float* Y0 = Yb;
    float* Y1 = Yb + (size_t)NRW * HD;
    float* Y2 = Yb + 2 * (size_t)NRW * HD;

    const int smemL0 = (128 * LDK + 2 * 16 * LDH) * 4;   // 166.4 KB
    const int smemL1 = (128 * LDK + 2 * 32 * LDH) * 4;   // 199.7 KB
    const int smemL2 = (128 * LDK + 1 * 64 * LDH) * 4;   // 199.7 KB
    cudaFuncSetAttribute((const void*)cseq_k<256, 256, 16, 2, true>,
                         cudaFuncAttributeMaxDynamicSharedMemorySize, smemL0);
    cudaFuncSetAttribute((const void*)cseq_k<128, 512, 32, 2, true>,
                         cudaFuncAttributeMaxDynamicSharedMemorySize, smemL1);
    cudaFuncSetAttribute((const void*)cseq_k<64, 1024, 64, 1, true>,
                         cudaFuncAttributeMaxDynamicSharedMemorySize, smemL2);
    cudaFuncSetAttribute((const void*)cseq_k<32, 2048, 64, 1, false>,
                         cudaFuncAttributeMaxDynamicSharedMemorySize, smemL2);

    k_prep<<<512, 256>>>(X, Wih00, bih00, bhh00, bih01, bhh01,
                         bih10, bhh10, bih11, bhh11);                      // 1
    bulk_k<32><<<dim3(8, 512), 256>>>(Xp, Wih0p, bRp + 0 * 16 * 1024, G0); // 2
    k_pad<<<1, 32>>>();                                                    // 3

    // 4 == profiled slot: L00 + fused projection for L01
    cseq_k<256, 256, 16, 2, true><<<128, 256, smemL0>>>(
        Whh00, G0, Y0, Wih01, bRp + 1 * 16 * 1024, G1);
    // L01 + fused projection for L10
    cseq_k<128, 512, 32, 2, true><<<128, 256, smemL1>>>(
        Whh01, G1, Y1, Wih10, bRp + 2 * 16 * 1024, G0);
    // L10 + fused projection for L11
    cseq_k<64, 1024, 64, 1, true><<<128, 256, smemL2>>>(
        Whh10, G0, Y0, Wih11, bRp + 3 * 16 * 1024, G1);
    // L11 (no epilogue)
    cseq_k<32, 2048, 64, 1, false><<<256, 256, smemL2>>>(
        Whh11, G1, Y2, Wih11, bRp, G0);

    // head: (Y2 + Y1) -> tanh(mlp) -> adapter
    head_k<<<NRW / 16, 256>>>(Y2, Y1, mlpw, mlpb, adw, adb, out);
}

// round 10
// speedup vs baseline: 2.0954x; 2.0954x over previous
#include <cuda_runtime.h>
#include <mma.h>

using namespace nvcuda;

#define NRW 65536
#define HD  256

// ---------------- static device buffers --------------------------------------
__device__ __align__(256) float g_Xp[NRW * 32];            // padded input (cols 20..31 = 0)
__device__ __align__(256) float g_Wih0[1024 * 32];         // padded W_ih_00
__device__ __align__(256) float g_bias[4][1024];           // b_ih + b_hh per layer
__device__ __align__(256) float g_G[(size_t)NRW * 1024];   // input preactivations
__device__ __align__(256) float g_Ybuf[3][(size_t)NRW * HD];
__device__ unsigned g_rdy[64];                             // per-row-group ready counters

typedef wmma::fragment<wmma::matrix_a, 16, 16, 8, wmma::precision::tf32, wmma::row_major> FragA;
typedef wmma::fragment<wmma::matrix_b, 16, 16, 8, wmma::precision::tf32, wmma::col_major> FragB;
typedef wmma::fragment<wmma::accumulator, 16, 16, 8, float> FragC;

__device__ __forceinline__ float sigf(float x) { return 1.0f / (1.0f + __expf(-x)); }

__device__ __forceinline__ void splitA(FragA& h, FragA& l) {
#pragma unroll
    for (int i = 0; i < h.num_elements; i++) {
        float v = h.x[i];
        float hh = wmma::__float_to_tf32(v);
        l.x[i] = wmma::__float_to_tf32(v - hh);
        h.x[i] = hh;
    }
}
__device__ __forceinline__ void splitB(FragB& h, FragB& l) {
#pragma unroll
    for (int i = 0; i < h.num_elements; i++) {
        float v = h.x[i];
        float hh = wmma::__float_to_tf32(v);
        l.x[i] = wmma::__float_to_tf32(v - hh);
        h.x[i] = hh;
    }
}
__device__ __forceinline__ void roundB(FragB& b) {
#pragma unroll
    for (int i = 0; i < b.num_elements; i++) b.x[i] = wmma::__float_to_tf32(b.x[i]);
}

// 3xTF32 K-loop (head kernel only)
__device__ __forceinline__ void kloop3(FragC& acc, const float* __restrict__ A, int lda,
                                       const float* __restrict__ B, int ldb, int K) {
    for (int k = 0; k < K; k += 8) {
        FragA ah, al;
        FragB bh, bl;
        wmma::load_matrix_sync(ah, A + k, lda);
        wmma::load_matrix_sync(bh, B + k, ldb);
        splitA(ah, al);
        splitB(bh, bl);
        wmma::mma_sync(acc, ah, bh, acc);
        wmma::mma_sync(acc, ah, bl, acc);
        wmma::mma_sync(acc, al, bh, acc);
    }
}

// 2xTF32 K-loop (split-A x rounded-B) — seq kernels
__device__ __forceinline__ void kloop2(FragC& acc, const float* __restrict__ A, int lda,
                                       const float* __restrict__ B, int ldb, int K) {
    for (int k = 0; k < K; k += 8) {
        FragA ah, al;
        FragB bh;
        wmma::load_matrix_sync(ah, A + k, lda);
        wmma::load_matrix_sync(bh, B + k, ldb);
        splitA(ah, al);
        roundB(bh);
        wmma::mma_sync(acc, ah, bh, acc);
        wmma::mma_sync(acc, al, bh, acc);
    }
}

// ---------------- prep: pad X / W_ih_00, combine biases ----------------------
__global__ void k_prep(const float* __restrict__ x, const float* __restrict__ wih0,
                       const float* __restrict__ bi0, const float* __restrict__ bh0,
                       const float* __restrict__ bi1, const float* __restrict__ bh1,
                       const float* __restrict__ bi2, const float* __restrict__ bh2,
                       const float* __restrict__ bi3, const float* __restrict__ bh3) {
    int tid = blockIdx.x * blockDim.x + threadIdx.x;
    int nt = gridDim.x * blockDim.x;
    for (int i = tid; i < NRW * 20; i += nt)
        g_Xp[(size_t)(i / 20) * 32 + (i % 20)] = x[i];
    for (int i = tid; i < 1024 * 20; i += nt)
        g_Wih0[(i / 20) * 32 + (i % 20)] = wih0[i];
    for (int i = tid; i < 1024; i += nt) {
        g_bias[0][i] = bi0[i] + bh0[i];
        g_bias[1][i] = bi1[i] + bh1[i];
        g_bias[2][i] = bi2[i] + bh2[i];
        g_bias[3][i] = bi3[i] + bh3[i];
    }
}

// ---------------- bulk GEMM v2: cp.async double-buffered ----------------------
// G = X @ W^T. BM=BN=128, BK=32, 256 threads, warp tile 32x64 (4x2 layout).
#define CPA16(dst, src) \
    asm volatile("cp.async.cg.shared.global [%0], [%1], 16;" :: "r"(dst), "l"(src))
#define CPA_COMMIT() asm volatile("cp.async.commit_group;" ::: "memory")
#define CPA_WAIT1()  asm volatile("cp.async.wait_group 1;" ::: "memory")
#define CPA_WAIT0()  asm volatile("cp.async.wait_group 0;" ::: "memory")

template <int K>
__global__ void __launch_bounds__(256, 1)
bulk2_k(const float* __restrict__ X, const float* __restrict__ W,
        float* __restrict__ G) {
    constexpr int NCH = K / 32;
    constexpr int LDS = 36;
    extern __shared__ float sm[];
    // layout: sA[2][128*LDS] then sB[2][128*LDS]
    float* sA[2] = { sm, sm + 128 * LDS };
    float* sB[2] = { sm + 2 * 128 * LDS, sm + 3 * 128 * LDS };

    const int n0 = blockIdx.x * 128;
    const size_t m0 = (size_t)blockIdx.y * 128;
    const int w = threadIdx.x >> 5;
    const int wr = (w >> 1) * 32;
    const int wc = (w & 1) * 64;

    // per-thread copy slots: 4 float4 per array
    const int s0 = threadIdx.x * 4;

    auto issue = [&](int chunk, int buf) {
        const int k0 = chunk * 32;
#pragma unroll
        for (int j = 0; j < 4; j++) {
            const int s = s0 + j;
            const int r = s >> 3;
            const int c4 = (s & 7) * 4;
            CPA16((unsigned)__cvta_generic_to_shared(sA[buf] + r * LDS + c4),
                  X + (m0 + r) * K + k0 + c4);
            CPA16((unsigned)__cvta_generic_to_shared(sB[buf] + r * LDS + c4),
                  W + (size_t)(n0 + r) * K + k0 + c4);
        }
        CPA_COMMIT();
    };

    FragC acc[2][4];
#pragma unroll
    for (int a = 0; a < 2; a++)
#pragma unroll
        for (int b = 0; b < 4; b++) wmma::fill_fragment(acc[a][b], 0.0f);

    issue(0, 0);
    for (int c = 0; c < NCH; c++) {
        const int buf = c & 1;
        if (c + 1 < NCH) {
            issue(c + 1, buf ^ 1);
            CPA_WAIT1();
        } else {
            CPA_WAIT0();
        }
        __syncthreads();
#pragma unroll
        for (int kk = 0; kk < 32; kk += 8) {
            FragA ah[2], al[2];
#pragma unroll
            for (int a = 0; a < 2; a++) {
                wmma::load_matrix_sync(ah[a], sA[buf] + (wr + a * 16) * LDS + kk, LDS);
                splitA(ah[a], al[a]);
            }
#pragma unroll
            for (int b = 0; b < 4; b++) {
                FragB bh;
                wmma::load_matrix_sync(bh, sB[buf] + (wc + b * 16) * LDS + kk, LDS);
                roundB(bh);
#pragma unroll
                for (int a = 0; a < 2; a++) {
                    wmma::mma_sync(acc[a][b], ah[a], bh, acc[a][b]);
                    wmma::mma_sync(acc[a][b], al[a], bh, acc[a][b]);
                }
            }
        }
        __syncthreads();
    }
#pragma unroll
    for (int a = 0; a < 2; a++)
#pragma unroll
        for (int b = 0; b < 4; b++)
            wmma::store_matrix_sync(G + (m0 + wr + a * 16) * 1024 + n0 + wc + b * 16,
                                    acc[a][b], 1024, wmma::mem_row_major);
}

// ---------------- persistent sequential LSTM (R4 structure, 2-MMA) -----------
// Block tile: TM rows x TH hidden units (TN = 4*TH gate cols).
// Row group rm syncs only with its C = 256/TH column-group peers.
template <int STEPS, int BEFF, int TM, int TH, int WM, int WN>
__global__ void __launch_bounds__(256, 1)
seq_k(const float* __restrict__ Whh, const float* __restrict__ G,
      const float* __restrict__ bias, float* __restrict__ Y,
      unsigned* __restrict__ rdy) {
    constexpr int TN = 4 * TH;
    constexpr int C = 256 / TH;
    constexpr int MA = TM / WM / 16;
    constexpr int NB = TN / WN / 16;
    constexpr int CPT = TM * TH / 256;
    extern __shared__ float sg[];   // [TM][TN], gate-major cols (g*TH + h)

    const int rm = blockIdx.x / C;
    const int cg = blockIdx.x % C;
    const int m0 = rm * TM;
    const int j0 = cg * TH;
    const int w = threadIdx.x >> 5;
    const int wr = (w / WN) * (TM / WM);
    const int wc = (w % WN) * (TN / WN);

    float cst[CPT];
#pragma unroll
    for (int q = 0; q < CPT; q++) cst[q] = 0.0f;

    for (int t = 0; t < STEPS; t++) {
        const size_t row0 = (size_t)t * BEFF + m0;
        if (t) {
            if (threadIdx.x == 0) {
                const unsigned tgt = (unsigned)C * (unsigned)t;
                while (*(volatile unsigned*)(rdy + rm) < tgt) __nanosleep(20);
                __threadfence();
            }
            __syncthreads();

            FragC acc[MA][NB];
#pragma unroll
            for (int a = 0; a < MA; a++)
#pragma unroll
                for (int b = 0; b < NB; b++) wmma::fill_fragment(acc[a][b], 0.0f);

            const float* Ab = Y + (row0 - BEFF) * HD;   // h_{t-1}, same rows
            for (int k0 = 0; k0 < HD; k0 += 8) {
                FragA ah[MA], al[MA];
#pragma unroll
                for (int a = 0; a < MA; a++) {
                    wmma::load_matrix_sync(ah[a], Ab + (size_t)(wr + a * 16) * HD + k0, HD);
                    splitA(ah[a], al[a]);
                }
#pragma unroll
                for (int b = 0; b < NB; b++) {
                    const int ncol = wc + b * 16;
                    const int gate = ncol / TH;
                    const int hoff = ncol % TH;
                    FragB bh;
                    wmma::load_matrix_sync(bh,
                        Whh + (size_t)(gate * 256 + j0 + hoff) * HD + k0, HD);
                    roundB(bh);
#pragma unroll
                    for (int a = 0; a < MA; a++) {
                        wmma::mma_sync(acc[a][b], ah[a], bh, acc[a][b]);
                        wmma::mma_sync(acc[a][b], al[a], bh, acc[a][b]);
                    }
                }
            }
#pragma unroll
            for (int a = 0; a < MA; a++)
#pragma unroll
                for (int b = 0; b < NB; b++)
                    wmma::store_matrix_sync(sg + (wr + a * 16) * TN + (wc + b * 16),
                                            acc[a][b], TN, wmma::mem_row_major);
            __syncthreads();
        }

        // ---- elementwise; c in registers ----
#pragma unroll
        for (int q = 0; q < CPT; q++) {
            const int e = threadIdx.x + q * 256;
            const int r = e / TH;
            const int h = e % TH;
            const size_t grow = (row0 + r) * 1024;
            float pi = G[grow + 0 * 256 + j0 + h] + bias[0 * 256 + j0 + h];
            float pf = G[grow + 1 * 256 + j0 + h] + bias[1 * 256 + j0 + h];
            float pg = G[grow + 2 * 256 + j0 + h] + bias[2 * 256 + j0 + h];
            float po = G[grow + 3 * 256 + j0 + h] + bias[3 * 256 + j0 + h];
            if (t) {
                pi += sg[r * TN + 0 * TH + h];
                pf += sg[r * TN + 1 * TH + h];
                pg += sg[r * TN + 2 * TH + h];
                po += sg[r * TN + 3 * TH + h];
            }
            const float cn = sigf(pf) * cst[q] + sigf(pi) * tanhf(pg);
            cst[q] = cn;
            Y[(row0 + r) * HD + j0 + h] = sigf(po) * tanhf(cn);
        }
        __syncthreads();
        if (threadIdx.x == 0) {
            __threadfence();
            atomicAdd(rdy + rm, 1u);
        }
    }
    // reset counter for next launch
    if (cg == 0 && threadIdx.x == 0) {
        const unsigned fin = (unsigned)C * (unsigned)STEPS;
        while (*(volatile unsigned*)(rdy + rm) < fin) __nanosleep(20);
        *(volatile unsigned*)(rdy + rm) = 0u;
        __threadfence();
    }
}

// ---------------- head: out = tanh((Y2+Y1) @ mlp_w^T + b) @ ad_w^T + ad_b ----
__global__ void __launch_bounds__(256, 2)
head_k(const float* __restrict__ Y2, const float* __restrict__ Y1,
       const float* __restrict__ mlpw, const float* __restrict__ mlpb,
       const float* __restrict__ adw, const float* __restrict__ adb,
       float* __restrict__ out) {
    __shared__ float sx[16][256];
    __shared__ float sh[16][256];
    __shared__ float so[16][48];

    const int warp = threadIdx.x >> 5;
    const size_t m0 = (size_t)blockIdx.x * 16;

    for (int e = threadIdx.x; e < 16 * 256; e += 256) {
        const size_t gi = m0 * 256 + e;
        sx[e / 256][e % 256] = Y2[gi] + Y1[gi];
    }
    __syncthreads();

    for (int st = warp; st < 16; st += 8) {
        FragC acc;
        wmma::fill_fragment(acc, 0.0f);
        kloop3(acc, &sx[0][0], 256, mlpw + (size_t)(st * 16) * 256, 256, 256);
        wmma::store_matrix_sync(&sh[0][st * 16], acc, 256, wmma::mem_row_major);
    }
    __syncthreads();
    for (int e = threadIdx.x; e < 16 * 256; e += 256)
        sh[e / 256][e % 256] = tanhf(sh[e / 256][e % 256] + mlpb[e % 256]);
    __syncthreads();

    if (warp < 3) {
        FragC acc;
        wmma::fill_fragment(acc, 0.0f);
        kloop3(acc, &sh[0][0], 256, adw + (size_t)(warp * 16) * 256, 256, 256);
        wmma::store_matrix_sync(&so[0][warp * 16], acc, 48, wmma::mem_row_major);
    }
    __syncthreads();
    for (int e = threadIdx.x; e < 16 * 48; e += 256)
        out[m0 * 48 + e] = so[e / 48][e % 48] + adb[e % 48];
}

// ---------------- host -------------------------------------------------------
extern "C" void kernel_launch(void* const* d_in, const int* in_sizes, int n_in,
                              void* d_out, int out_size) {
    const float* X     = (const float*)d_in[0];
    const float* Wih00 = (const float*)d_in[1];
    const float* Whh00 = (const float*)d_in[2];
    const float* bih00 = (const float*)d_in[3];
    const float* bhh00 = (const float*)d_in[4];
    const float* Wih01 = (const float*)d_in[5];
    const float* Whh01 = (const float*)d_in[6];
    const float* bih01 = (const float*)d_in[7];
    const float* bhh01 = (const float*)d_in[8];
    const float* Wih10 = (const float*)d_in[9];
    const float* Whh10 = (const float*)d_in[10];
    const float* bih10 = (const float*)d_in[11];
    const float* bhh10 = (const float*)d_in[12];
    const float* Wih11 = (const float*)d_in[13];
    const float* Whh11 = (const float*)d_in[14];
    const float* bih11 = (const float*)d_in[15];
    const float* bhh11 = (const float*)d_in[16];
    const float* mlpw  = (const float*)d_in[17];
    const float* mlpb  = (const float*)d_in[18];
    const float* adw   = (const float*)d_in[19];
    const float* adb   = (const float*)d_in[20];
    float* out = (float*)d_out;

    float *Xp, *Wih0p, *biasp, *Gp, *Yb;
    unsigned* rdyp;
    cudaGetSymbolAddress((void**)&Xp, g_Xp);
    cudaGetSymbolAddress((void**)&Wih0p, g_Wih0);
    cudaGetSymbolAddress((void**)&biasp, g_bias);
    cudaGetSymbolAddress((void**)&Gp, g_G);
    cudaGetSymbolAddress((void**)&Yb, g_Ybuf);
    cudaGetSymbolAddress((void**)&rdyp, g_rdy);
    float* Y0 = Yb;
    float* Y1 = Yb + (size_t)NRW * HD;
    float* Y2 = Yb + 2 * (size_t)NRW * HD;

    const int bsm = 4 * 128 * 36 * 4;   // 73.7 KB dynamic
    cudaFuncSetAttribute((const void*)bulk2_k<32>,
                         cudaFuncAttributeMaxDynamicSharedMemorySize, bsm);
    cudaFuncSetAttribute((const void*)bulk2_k<256>,
                         cudaFuncAttributeMaxDynamicSharedMemorySize, bsm);
    cudaFuncSetAttribute((const void*)seq_k<256, 256, 16, 32, 1, 8>,
                         cudaFuncAttributeMaxDynamicSharedMemorySize, 16 * 128 * 4);
    cudaFuncSetAttribute((const void*)seq_k<128, 512, 32, 32, 2, 4>,
                         cudaFuncAttributeMaxDynamicSharedMemorySize, 32 * 128 * 4);
    cudaFuncSetAttribute((const void*)seq_k<64, 1024, 32, 64, 2, 4>,
                         cudaFuncAttributeMaxDynamicSharedMemorySize, 32 * 256 * 4);
    cudaFuncSetAttribute((const void*)seq_k<32, 2048, 64, 64, 2, 4>,
                         cudaFuncAttributeMaxDynamicSharedMemorySize, 64 * 256 * 4);

    k_prep<<<512, 256>>>(X, Wih00, bih00, bhh00, bih01, bhh01,
                         bih10, bhh10, bih11, bhh11);

    dim3 bgrid(8, 512);

    // ---- group 0 ----
    bulk2_k<32><<<bgrid, 256, bsm>>>(Xp, Wih0p, Gp);
    seq_k<256, 256, 16, 32, 1, 8><<<128, 256, 16 * 128 * 4>>>(
        Whh00, Gp, biasp + 0 * 1024, Y0, rdyp);

    bulk2_k<256><<<bgrid, 256, bsm>>>(Y0, Wih01, Gp);
    seq_k<128, 512, 32, 32, 2, 4><<<128, 256, 32 * 128 * 4>>>(
        Whh01, Gp, biasp + 1 * 1024, Y1, rdyp);

    // ---- group 1 ----
    bulk2_k<256><<<bgrid, 256, bsm>>>(Y1, Wih10, Gp);
    seq_k<64, 1024, 32, 64, 2, 4><<<128, 256, 32 * 256 * 4>>>(
        Whh10, Gp, biasp + 2 * 1024, Y0, rdyp);

    bulk2_k<256><<<bgrid, 256, bsm>>>(Y0, Wih11, Gp);
    seq_k<32, 2048, 64, 64, 2, 4><<<128, 256, 64 * 256 * 4>>>(
        Whh11, Gp, biasp + 3 * 1024, Y2, rdyp);

    // head: (Y2 + Y1) -> tanh(mlp) -> adapter
    head_k<<<NRW / 16, 256>>>(Y2, Y1, mlpw, mlpb, adw, adb, out);
}

// round 11
// speedup vs baseline: 2.2167x; 1.0579x over previous
#include <cuda_runtime.h>
#include <mma.h>

using namespace nvcuda;

#define NRW 65536
#define HD  256

// ---------------- static device buffers --------------------------------------
__device__ __align__(256) float g_Xp[NRW * 32];             // padded input (cols 20..31 = 0)
__device__ __align__(256) float g_Wih0[1024 * 32];          // padded W_ih_00
__device__ __align__(256) float g_biasRep[4][16 * 1024];    // 16 replicated rows (b_ih+b_hh)
__device__ __align__(256) float g_G[(size_t)NRW * 1024];    // input preacts (+bias)
__device__ __align__(256) float g_Ybuf[3][(size_t)NRW * HD];
__device__ unsigned g_rdy[64];                              // per-row-group ready counters

typedef wmma::fragment<wmma::matrix_a, 16, 16, 8, wmma::precision::tf32, wmma::row_major> FragA;
typedef wmma::fragment<wmma::matrix_b, 16, 16, 8, wmma::precision::tf32, wmma::col_major> FragB;
typedef wmma::fragment<wmma::accumulator, 16, 16, 8, float> FragC;

__device__ __forceinline__ float sigf(float x) { return 1.0f / (1.0f + __expf(-x)); }

__device__ __forceinline__ void splitA(FragA& h, FragA& l) {
#pragma unroll
    for (int i = 0; i < h.num_elements; i++) {
        float v = h.x[i];
        float hh = wmma::__float_to_tf32(v);
        l.x[i] = wmma::__float_to_tf32(v - hh);
        h.x[i] = hh;
    }
}
__device__ __forceinline__ void splitB(FragB& h, FragB& l) {
#pragma unroll
    for (int i = 0; i < h.num_elements; i++) {
        float v = h.x[i];
        float hh = wmma::__float_to_tf32(v);
        l.x[i] = wmma::__float_to_tf32(v - hh);
        h.x[i] = hh;
    }
}
__device__ __forceinline__ void roundB(FragB& b) {
#pragma unroll
    for (int i = 0; i < b.num_elements; i++) b.x[i] = wmma::__float_to_tf32(b.x[i]);
}

// 3xTF32 K-loop (head kernel only)
__device__ __forceinline__ void kloop3(FragC& acc, const float* __restrict__ A, int lda,
                                       const float* __restrict__ B, int ldb, int K) {
    for (int k = 0; k < K; k += 8) {
        FragA ah, al;
        FragB bh, bl;
        wmma::load_matrix_sync(ah, A + k, lda);
        wmma::load_matrix_sync(bh, B + k, ldb);
        splitA(ah, al);
        splitB(bh, bl);
        wmma::mma_sync(acc, ah, bh, acc);
        wmma::mma_sync(acc, ah, bl, acc);
        wmma::mma_sync(acc, al, bh, acc);
    }
}

// ---------------- prep: pad X / W_ih_00, replicated bias rows ----------------
__global__ void k_prep(const float* __restrict__ x, const float* __restrict__ wih0,
                       const float* __restrict__ bi0, const float* __restrict__ bh0,
                       const float* __restrict__ bi1, const float* __restrict__ bh1,
                       const float* __restrict__ bi2, const float* __restrict__ bh2,
                       const float* __restrict__ bi3, const float* __restrict__ bh3) {
    int tid = blockIdx.x * blockDim.x + threadIdx.x;
    int nt = gridDim.x * blockDim.x;
    for (int i = tid; i < NRW * 20; i += nt)
        g_Xp[(size_t)(i / 20) * 32 + (i % 20)] = x[i];
    for (int i = tid; i < 1024 * 20; i += nt)
        g_Wih0[(i / 20) * 32 + (i % 20)] = wih0[i];
    for (int i = tid; i < 16 * 1024; i += nt) {
        int c = i % 1024;
        g_biasRep[0][i] = bi0[c] + bh0[c];
        g_biasRep[1][i] = bi1[c] + bh1[c];
        g_biasRep[2][i] = bi2[c] + bh2[c];
        g_biasRep[3][i] = bi3[c] + bh3[c];
    }
}

__global__ void k_pad() {}

// ---------------- bulk GEMM: cp.async double-buffered, G = X@W^T + bias -------
#define CPA16(dst, src) \
    asm volatile("cp.async.cg.shared.global [%0], [%1], 16;" :: "r"(dst), "l"(src))
#define CPA_COMMIT() asm volatile("cp.async.commit_group;" ::: "memory")
#define CPA_WAIT1()  asm volatile("cp.async.wait_group 1;" ::: "memory")
#define CPA_WAIT0()  asm volatile("cp.async.wait_group 0;" ::: "memory")

template <int K>
__global__ void __launch_bounds__(256, 1)
bulk2_k(const float* __restrict__ X, const float* __restrict__ W,
        const float* __restrict__ bR, float* __restrict__ G) {
    constexpr int NCH = K / 32;
    constexpr int LDS = 36;
    extern __shared__ float sm[];
    float* sA[2] = { sm, sm + 128 * LDS };
    float* sB[2] = { sm + 2 * 128 * LDS, sm + 3 * 128 * LDS };

    const int n0 = blockIdx.x * 128;
    const size_t m0 = (size_t)blockIdx.y * 128;
    const int w = threadIdx.x >> 5;
    const int wr = (w >> 1) * 32;
    const int wc = (w & 1) * 64;
    const int s0 = threadIdx.x * 4;

    auto issue = [&](int chunk, int buf) {
        const int k0 = chunk * 32;
#pragma unroll
        for (int j = 0; j < 4; j++) {
            const int s = s0 + j;
            const int r = s >> 3;
            const int c4 = (s & 7) * 4;
            CPA16((unsigned)__cvta_generic_to_shared(sA[buf] + r * LDS + c4),
                  X + (m0 + r) * K + k0 + c4);
            CPA16((unsigned)__cvta_generic_to_shared(sB[buf] + r * LDS + c4),
                  W + (size_t)(n0 + r) * K + k0 + c4);
        }
        CPA_COMMIT();
    };

    FragC acc[2][4];
#pragma unroll
    for (int a = 0; a < 2; a++)
#pragma unroll
        for (int b = 0; b < 4; b++) wmma::fill_fragment(acc[a][b], 0.0f);

    issue(0, 0);
    for (int c = 0; c < NCH; c++) {
        const int buf = c & 1;
        if (c + 1 < NCH) {
            issue(c + 1, buf ^ 1);
            CPA_WAIT1();
        } else {
            CPA_WAIT0();
        }
        __syncthreads();
#pragma unroll
        for (int kk = 0; kk < 32; kk += 8) {
            FragA ah[2], al[2];
#pragma unroll
            for (int a = 0; a < 2; a++) {
                wmma::load_matrix_sync(ah[a], sA[buf] + (wr + a * 16) * LDS + kk, LDS);
                splitA(ah[a], al[a]);
            }
#pragma unroll
            for (int b = 0; b < 4; b++) {
                FragB bh;
                wmma::load_matrix_sync(bh, sB[buf] + (wc + b * 16) * LDS + kk, LDS);
                roundB(bh);
#pragma unroll
                for (int a = 0; a < 2; a++) {
                    wmma::mma_sync(acc[a][b], ah[a], bh, acc[a][b]);
                    wmma::mma_sync(acc[a][b], al[a], bh, acc[a][b]);
                }
            }
        }
        __syncthreads();
    }
#pragma unroll
    for (int b = 0; b < 4; b++) {
        FragC bf;
        wmma::load_matrix_sync(bf, bR + n0 + wc + b * 16, 1024, wmma::mem_row_major);
#pragma unroll
        for (int a = 0; a < 2; a++) {
#pragma unroll
            for (int i = 0; i < bf.num_elements; i++) acc[a][b].x[i] += bf.x[i];
            wmma::store_matrix_sync(G + (m0 + wr + a * 16) * 1024 + n0 + wc + b * 16,
                                    acc[a][b], 1024, wmma::mem_row_major);
        }
    }
}

// ---------------- persistent sequential LSTM (2-MMA, unrolled, G-prefetch) ----
// Block tile: TM rows x TH hidden units (TN = 4*TH gate cols).
// Row group rm syncs only with its C = 256/TH column-group peers.
template <int STEPS, int BEFF, int TM, int TH, int WM, int WN>
__global__ void __launch_bounds__(256, 1)
seq_k(const float* __restrict__ Whh, const float* __restrict__ G,
      float* __restrict__ Y, unsigned* __restrict__ rdy) {
    constexpr int TN = 4 * TH;
    constexpr int C = 256 / TH;
    constexpr int MA = TM / WM / 16;
    constexpr int NB = TN / WN / 16;
    constexpr int CPT = TM * TH / 256;
    extern __shared__ float sg[];   // [TM][TN], gate-major cols (g*TH + h)

    const int rm = blockIdx.x / C;
    const int cg = blockIdx.x % C;
    const int m0 = rm * TM;
    const int j0 = cg * TH;
    const int w = threadIdx.x >> 5;
    const int wr = (w / WN) * (TM / WM);
    const int wc = (w % WN) * (TN / WN);

    float cst[CPT];
#pragma unroll
    for (int q = 0; q < CPT; q++) cst[q] = 0.0f;

    for (int t = 0; t < STEPS; t++) {
        const size_t row0 = (size_t)t * BEFF + m0;

        // ---- prefetch this step's G (+bias) into registers, pre-wait ----
        float gp[CPT][4];
#pragma unroll
        for (int q = 0; q < CPT; q++) {
            const int e = threadIdx.x + q * 256;
            const int r = e / TH;
            const int h = e % TH;
            const size_t grow = (row0 + r) * 1024 + j0 + h;
#pragma unroll
            for (int g = 0; g < 4; g++) gp[q][g] = G[grow + g * 256];
        }

        if (t) {
            if (threadIdx.x == 0) {
                const unsigned tgt = (unsigned)C * (unsigned)t;
                while (*(volatile unsigned*)(rdy + rm) < tgt) __nanosleep(20);
                __threadfence();
            }
            __syncthreads();

            FragC acc[MA][NB];
#pragma unroll
            for (int a = 0; a < MA; a++)
#pragma unroll
                for (int b = 0; b < NB; b++) wmma::fill_fragment(acc[a][b], 0.0f);

            const float* Ab = Y + (row0 - BEFF) * HD;   // h_{t-1}, same rows
#pragma unroll 2
            for (int k0 = 0; k0 < HD; k0 += 8) {
                FragA ah[MA], al[MA];
#pragma unroll
                for (int a = 0; a < MA; a++) {
                    wmma::load_matrix_sync(ah[a], Ab + (size_t)(wr + a * 16) * HD + k0, HD);
                    splitA(ah[a], al[a]);
                }
#pragma unroll
                for (int b = 0; b < NB; b++) {
                    const int ncol = wc + b * 16;
                    const int gate = ncol / TH;
                    const int hoff = ncol % TH;
                    FragB bh;
                    wmma::load_matrix_sync(bh,
                        Whh + (size_t)(gate * 256 + j0 + hoff) * HD + k0, HD);
                    roundB(bh);
#pragma unroll
                    for (int a = 0; a < MA; a++) {
                        wmma::mma_sync(acc[a][b], ah[a], bh, acc[a][b]);
                        wmma::mma_sync(acc[a][b], al[a], bh, acc[a][b]);
                    }
                }
            }
#pragma unroll
            for (int a = 0; a < MA; a++)
#pragma unroll
                for (int b = 0; b < NB; b++)
                    wmma::store_matrix_sync(sg + (wr + a * 16) * TN + (wc + b * 16),
                                            acc[a][b], TN, wmma::mem_row_major);
            __syncthreads();
        }

        // ---- elementwise; c in registers; G already in gp ----
#pragma unroll
        for (int q = 0; q < CPT; q++) {
            const int e = threadIdx.x + q * 256;
            const int r = e / TH;
            const int h = e % TH;
            float pi = gp[q][0];
            float pf = gp[q][1];
            float pg = gp[q][2];
            float po = gp[q][3];
            if (t) {
                pi += sg[r * TN + 0 * TH + h];
                pf += sg[r * TN + 1 * TH + h];
                pg += sg[r * TN + 2 * TH + h];
                po += sg[r * TN + 3 * TH + h];
            }
            const float cn = sigf(pf) * cst[q] + sigf(pi) * tanhf(pg);
            cst[q] = cn;
            Y[(row0 + r) * HD + j0 + h] = sigf(po) * tanhf(cn);
        }
        __syncthreads();
        if (threadIdx.x == 0) {
            __threadfence();
            atomicAdd(rdy + rm, 1u);
        }
    }
    // reset counter for next launch
    if (cg == 0 && threadIdx.x == 0) {
        const unsigned fin = (unsigned)C * (unsigned)STEPS;
        while (*(volatile unsigned*)(rdy + rm) < fin) __nanosleep(20);
        *(volatile unsigned*)(rdy + rm) = 0u;
        __threadfence();
    }
}

// ---------------- head: out = tanh((Y2+Y1) @ mlp_w^T + b) @ ad_w^T + ad_b ----
__global__ void __launch_bounds__(256, 2)
head_k(const float* __restrict__ Y2, const float* __restrict__ Y1,
       const float* __restrict__ mlpw, const float* __restrict__ mlpb,
       const float* __restrict__ adw, const float* __restrict__ adb,
       float* __restrict__ out) {
    __shared__ float sx[16][256];
    __shared__ float sh[16][256];
    __shared__ float so[16][48];

    const int warp = threadIdx.x >> 5;
    const size_t m0 = (size_t)blockIdx.x * 16;

    for (int e = threadIdx.x; e < 16 * 256; e += 256) {
        const size_t gi = m0 * 256 + e;
        sx[e / 256][e % 256] = Y2[gi] + Y1[gi];
    }
    __syncthreads();

    for (int st = warp; st < 16; st += 8) {
        FragC acc;
        wmma::fill_fragment(acc, 0.0f);
        kloop3(acc, &sx[0][0], 256, mlpw + (size_t)(st * 16) * 256, 256, 256);
        wmma::store_matrix_sync(&sh[0][st * 16], acc, 256, wmma::mem_row_major);
    }
    __syncthreads();
    for (int e = threadIdx.x; e < 16 * 256; e += 256)
        sh[e / 256][e % 256] = tanhf(sh[e / 256][e % 256] + mlpb[e % 256]);
    __syncthreads();

    if (warp < 3) {
        FragC acc;
        wmma::fill_fragment(acc, 0.0f);
        kloop3(acc, &sh[0][0], 256, adw + (size_t)(warp * 16) * 256, 256, 256);
        wmma::store_matrix_sync(&so[0][warp * 16], acc, 48, wmma::mem_row_major);
    }
    __syncthreads();
    for (int e = threadIdx.x; e < 16 * 48; e += 256)
        out[m0 * 48 + e] = so[e / 48][e % 48] + adb[e % 48];
}

// ---------------- host -------------------------------------------------------
extern "C" void kernel_launch(void* const* d_in, const int* in_sizes, int n_in,
                              void* d_out, int out_size) {
    const float* X     = (const float*)d_in[0];
    const float* Wih00 = (const float*)d_in[1];
    const float* Whh00 = (const float*)d_in[2];
    const float* bih00 = (const float*)d_in[3];
    const float* bhh00 = (const float*)d_in[4];
    const float* Wih01 = (const float*)d_in[5];
    const float* Whh01 = (const float*)d_in[6];
    const float* bih01 = (const float*)d_in[7];
    const float* bhh01 = (const float*)d_in[8];
    const float* Wih10 = (const float*)d_in[9];
    const float* Whh10 = (const float*)d_in[10];
    const float* bih10 = (const float*)d_in[11];
    const float* bhh10 = (const float*)d_in[12];
    const float* Wih11 = (const float*)d_in[13];
    const float* Whh11 = (const float*)d_in[14];
    const float* bih11 = (const float*)d_in[15];
    const float* bhh11 = (const float*)d_in[16];
    const float* mlpw  = (const float*)d_in[17];
    const float* mlpb  = (const float*)d_in[18];
    const float* adw   = (const float*)d_in[19];
    const float* adb   = (const float*)d_in[20];
    float* out = (float*)d_out;

    float *Xp, *Wih0p, *bRp, *Gp, *Yb;
    unsigned* rdyp;
    cudaGetSymbolAddress((void**)&Xp, g_Xp);
    cudaGetSymbolAddress((void**)&Wih0p, g_Wih0);
    cudaGetSymbolAddress((void**)&bRp, g_biasRep);
    cudaGetSymbolAddress((void**)&Gp, g_G);
    cudaGetSymbolAddress((void**)&Yb, g_Ybuf);
    cudaGetSymbolAddress((void**)&rdyp, g_rdy);
    float* Y0 = Yb;
    float* Y1 = Yb + (size_t)NRW * HD;
    float* Y2 = Yb + 2 * (size_t)NRW * HD;

    const int bsm = 4 * 128 * 36 * 4;   // 73.7 KB dynamic
    cudaFuncSetAttribute((const void*)bulk2_k<32>,
                         cudaFuncAttributeMaxDynamicSharedMemorySize, bsm);
    cudaFuncSetAttribute((const void*)bulk2_k<256>,
                         cudaFuncAttributeMaxDynamicSharedMemorySize, bsm);
    cudaFuncSetAttribute((const void*)seq_k<256, 256, 16, 32, 1, 8>,
                         cudaFuncAttributeMaxDynamicSharedMemorySize, 16 * 128 * 4);
    cudaFuncSetAttribute((const void*)seq_k<128, 512, 32, 32, 2, 4>,
                         cudaFuncAttributeMaxDynamicSharedMemorySize, 32 * 128 * 4);
    cudaFuncSetAttribute((const void*)seq_k<64, 1024, 32, 64, 2, 4>,
                         cudaFuncAttributeMaxDynamicSharedMemorySize, 32 * 256 * 4);
    cudaFuncSetAttribute((const void*)seq_k<32, 2048, 64, 64, 2, 4>,
                         cudaFuncAttributeMaxDynamicSharedMemorySize, 64 * 256 * 4);

    dim3 bgrid(8, 512);

    k_prep<<<512, 256>>>(X, Wih00, bih00, bhh00, bih01, bhh01,
                         bih10, bhh10, bih11, bhh11);                       // 1
    bulk2_k<32><<<bgrid, 256, bsm>>>(Xp, Wih0p, bRp + 0 * 16 * 1024, Gp);   // 2
    k_pad<<<1, 32>>>();                                                     // 3

    // 4 == profiled slot: seq L0
    seq_k<256, 256, 16, 32, 1, 8><<<128, 256, 16 * 128 * 4>>>(
        Whh00, Gp, Y0, rdyp);

    bulk2_k<256><<<bgrid, 256, bsm>>>(Y0, Wih01, bRp + 1 * 16 * 1024, Gp);
    seq_k<128, 512, 32, 32, 2, 4><<<128, 256, 32 * 128 * 4>>>(
        Whh01, Gp, Y1, rdyp);

    bulk2_k<256><<<bgrid, 256, bsm>>>(Y1, Wih10, bRp + 2 * 16 * 1024, Gp);
    seq_k<64, 1024, 32, 64, 2, 4><<<128, 256, 32 * 256 * 4>>>(
        Whh10, Gp, Y0, rdyp);

    bulk2_k<256><<<bgrid, 256, bsm>>>(Y0, Wih11, bRp + 3 * 16 * 1024, Gp);
    seq_k<32, 2048, 64, 64, 2, 4><<<128, 256, 64 * 256 * 4>>>(
        Whh11, Gp, Y2, rdyp);

    // head: (Y2 + Y1) -> tanh(mlp) -> adapter
    head_k<<<NRW / 16, 256>>>(Y2, Y1, mlpw, mlpb, adw, adb, out);
}

// round 12
// speedup vs baseline: 2.4132x; 1.0887x over previous
#include <cuda_runtime.h>
#include <mma.h>

using namespace nvcuda;

#define NRW 65536
#define HD  256

// ---------------- static device buffers --------------------------------------
__device__ __align__(256) float g_Xp[NRW * 32];             // padded input (cols 20..31 = 0)
__device__ __align__(256) float g_Wih0[1024 * 32];          // padded W_ih_00
__device__ __align__(256) float g_biasRep[4][16 * 1024];    // 16 replicated rows (b_ih+b_hh)
__device__ __align__(256) float g_G[(size_t)NRW * 1024];    // input preacts (+bias)
__device__ __align__(256) float g_Ybuf[3][(size_t)NRW * HD];
__device__ unsigned g_rdy[64];                              // per-row-group ready counters

typedef wmma::fragment<wmma::matrix_a, 16, 16, 8, wmma::precision::tf32, wmma::row_major> FragA;
typedef wmma::fragment<wmma::matrix_b, 16, 16, 8, wmma::precision::tf32, wmma::col_major> FragB;
typedef wmma::fragment<wmma::accumulator, 16, 16, 8, float> FragC;

__device__ __forceinline__ float sigf(float x) { return 1.0f / (1.0f + __expf(-x)); }

__device__ __forceinline__ void splitA(FragA& h, FragA& l) {
#pragma unroll
    for (int i = 0; i < h.num_elements; i++) {
        float v = h.x[i];
        float hh = wmma::__float_to_tf32(v);
        l.x[i] = wmma::__float_to_tf32(v - hh);
        h.x[i] = hh;
    }
}
__device__ __forceinline__ void splitB(FragB& h, FragB& l) {
#pragma unroll
    for (int i = 0; i < h.num_elements; i++) {
        float v = h.x[i];
        float hh = wmma::__float_to_tf32(v);
        l.x[i] = wmma::__float_to_tf32(v - hh);
        h.x[i] = hh;
    }
}
__device__ __forceinline__ void roundB(FragB& b) {
#pragma unroll
    for (int i = 0; i < b.num_elements; i++) b.x[i] = wmma::__float_to_tf32(b.x[i]);
}

// 3xTF32 K-loop (head kernel only)
__device__ __forceinline__ void kloop3(FragC& acc, const float* __restrict__ A, int lda,
                                       const float* __restrict__ B, int ldb, int K) {
    for (int k = 0; k < K; k += 8) {
        FragA ah, al;
        FragB bh, bl;
        wmma::load_matrix_sync(ah, A + k, lda);
        wmma::load_matrix_sync(bh, B + k, ldb);
        splitA(ah, al);
        splitB(bh, bl);
        wmma::mma_sync(acc, ah, bh, acc);
        wmma::mma_sync(acc, ah, bl, acc);
        wmma::mma_sync(acc, al, bh, acc);
    }
}

// ---------------- prep: pad X / W_ih_00, replicated bias rows ----------------
__global__ void k_prep(const float* __restrict__ x, const float* __restrict__ wih0,
                       const float* __restrict__ bi0, const float* __restrict__ bh0,
                       const float* __restrict__ bi1, const float* __restrict__ bh1,
                       const float* __restrict__ bi2, const float* __restrict__ bh2,
                       const float* __restrict__ bi3, const float* __restrict__ bh3) {
    int tid = blockIdx.x * blockDim.x + threadIdx.x;
    int nt = gridDim.x * blockDim.x;
    for (int i = tid; i < NRW * 20; i += nt)
        g_Xp[(size_t)(i / 20) * 32 + (i % 20)] = x[i];
    for (int i = tid; i < 1024 * 20; i += nt)
        g_Wih0[(i / 20) * 32 + (i % 20)] = wih0[i];
    for (int i = tid; i < 16 * 1024; i += nt) {
        int c = i % 1024;
        g_biasRep[0][i] = bi0[c] + bh0[c];
        g_biasRep[1][i] = bi1[c] + bh1[c];
        g_biasRep[2][i] = bi2[c] + bh2[c];
        g_biasRep[3][i] = bi3[c] + bh3[c];
    }
}

__global__ void k_pad() {}

// ---------------- bulk GEMM: cp.async double-buffered, G = X@W^T + bias -------
#define CPA16(dst, src) \
    asm volatile("cp.async.cg.shared.global [%0], [%1], 16;" :: "r"(dst), "l"(src))
#define CPA_COMMIT() asm volatile("cp.async.commit_group;" ::: "memory")
#define CPA_WAIT1()  asm volatile("cp.async.wait_group 1;" ::: "memory")
#define CPA_WAIT0()  asm volatile("cp.async.wait_group 0;" ::: "memory")

template <int K>
__global__ void __launch_bounds__(256, 1)
bulk2_k(const float* __restrict__ X, const float* __restrict__ W,
        const float* __restrict__ bR, float* __restrict__ G) {
    constexpr int NCH = K / 32;
    constexpr int LDS = 36;
    extern __shared__ float sm[];
    float* sA[2] = { sm, sm + 128 * LDS };
    float* sB[2] = { sm + 2 * 128 * LDS, sm + 3 * 128 * LDS };

    const int n0 = blockIdx.x * 128;
    const size_t m0 = (size_t)blockIdx.y * 128;
    const int w = threadIdx.x >> 5;
    const int wr = (w >> 1) * 32;
    const int wc = (w & 1) * 64;
    const int s0 = threadIdx.x * 4;

    auto issue = [&](int chunk, int buf) {
        const int k0 = chunk * 32;
#pragma unroll
        for (int j = 0; j < 4; j++) {
            const int s = s0 + j;
            const int r = s >> 3;
            const int c4 = (s & 7) * 4;
            CPA16((unsigned)__cvta_generic_to_shared(sA[buf] + r * LDS + c4),
                  X + (m0 + r) * K + k0 + c4);
            CPA16((unsigned)__cvta_generic_to_shared(sB[buf] + r * LDS + c4),
                  W + (size_t)(n0 + r) * K + k0 + c4);
        }
        CPA_COMMIT();
    };

    FragC acc[2][4];
#pragma unroll
    for (int a = 0; a < 2; a++)
#pragma unroll
        for (int b = 0; b < 4; b++) wmma::fill_fragment(acc[a][b], 0.0f);

    issue(0, 0);
    for (int c = 0; c < NCH; c++) {
        const int buf = c & 1;
        if (c + 1 < NCH) {
            issue(c + 1, buf ^ 1);
            CPA_WAIT1();
        } else {
            CPA_WAIT0();
        }
        __syncthreads();
#pragma unroll
        for (int kk = 0; kk < 32; kk += 8) {
            FragA ah[2], al[2];
#pragma unroll
            for (int a = 0; a < 2; a++) {
                wmma::load_matrix_sync(ah[a], sA[buf] + (wr + a * 16) * LDS + kk, LDS);
                splitA(ah[a], al[a]);
            }
#pragma unroll
            for (int b = 0; b < 4; b++) {
                FragB bh;
                wmma::load_matrix_sync(bh, sB[buf] + (wc + b * 16) * LDS + kk, LDS);
                roundB(bh);
#pragma unroll
                for (int a = 0; a < 2; a++) {
                    wmma::mma_sync(acc[a][b], ah[a], bh, acc[a][b]);
                    wmma::mma_sync(acc[a][b], al[a], bh, acc[a][b]);
                }
            }
        }
        __syncthreads();
    }
#pragma unroll
    for (int b = 0; b < 4; b++) {
        FragC bf;
        wmma::load_matrix_sync(bf, bR + n0 + wc + b * 16, 1024, wmma::mem_row_major);
#pragma unroll
        for (int a = 0; a < 2; a++) {
#pragma unroll
            for (int i = 0; i < bf.num_elements; i++) acc[a][b].x[i] += bf.x[i];
            wmma::store_matrix_sync(G + (m0 + wr + a * 16) * 1024 + n0 + wc + b * 16,
                                    acc[a][b], 1024, wmma::mem_row_major);
        }
    }
}

// ---------------- persistent sequential LSTM: Whh resident in registers ------
// TH=32: block owns TM rows x 32 hidden cols (128 gate cols). 8 warps, each
// owns one 16-col gate chunk (gate = w>>1, half = w&1) for ALL row tiles.
// B (Whh slice) = 32 fragments/warp, loaded + tf32-rounded ONCE per layer.
// Per step: only A (h_{t-1}) is loaded; full unroll gives high MLP.
template <int STEPS, int BEFF, int TM, bool GPF>
__global__ void __launch_bounds__(256, 1)
seq_k(const float* __restrict__ Whh, const float* __restrict__ G,
      float* __restrict__ Y, unsigned* __restrict__ rdy) {
    constexpr int TN = 128;
    constexpr int C = 8;
    constexpr int MA = TM / 16;
    constexpr int CPT = TM * 32 / 256;
    extern __shared__ float sg[];   // [TM][TN], gate-major cols (g*32 + h)

    const int rm = blockIdx.x / C;
    const int cg = blockIdx.x % C;
    const int m0 = rm * TM;
    const int j0 = cg * 32;
    const int w = threadIdx.x >> 5;
    const int gate = w >> 1;
    const int hoff = (w & 1) * 16;

    // ---- load Whh fragments once (tf32-rounded) ----
    FragB Bf[32];
    {
        const float* Brow = Whh + (size_t)(gate * 256 + j0 + hoff) * HD;
#pragma unroll
        for (int k = 0; k < 32; k++) {
            wmma::load_matrix_sync(Bf[k], Brow + k * 8, HD);
            roundB(Bf[k]);
        }
    }

    float cst[CPT];
#pragma unroll
    for (int q = 0; q < CPT; q++) cst[q] = 0.0f;

    for (int t = 0; t < STEPS; t++) {
        const size_t row0 = (size_t)t * BEFF + m0;

        // optional register prefetch of G (pre-wait)
        float gp[GPF ? CPT : 1][4];
        if (GPF) {
#pragma unroll
            for (int q = 0; q < CPT; q++) {
                const int e = threadIdx.x + q * 256;
                const size_t grow = (row0 + e / 32) * 1024 + j0 + (e & 31);
#pragma unroll
                for (int g = 0; g < 4; g++) gp[q][g] = G[grow + g * 256];
            }
        }

        if (t) {
            if (threadIdx.x == 0) {
                const unsigned tgt = (unsigned)C * (unsigned)t;
                while (*(volatile unsigned*)(rdy + rm) < tgt) __nanosleep(20);
                __threadfence();
            }
            __syncthreads();

            FragC acc[MA], accB;
#pragma unroll
            for (int a = 0; a < MA; a++) wmma::fill_fragment(acc[a], 0.0f);
            if (MA == 1) wmma::fill_fragment(accB, 0.0f);

            const float* Ab = Y + (row0 - BEFF) * HD;   // h_{t-1}, same rows
#pragma unroll
            for (int k = 0; k < 32; k++) {
#pragma unroll
                for (int a = 0; a < MA; a++) {
                    FragA ah, al;
                    wmma::load_matrix_sync(ah, Ab + (size_t)(a * 16) * HD + k * 8, HD);
                    splitA(ah, al);
                    if (MA == 1 && (k & 1)) {
                        wmma::mma_sync(accB, ah, Bf[k], accB);
                        wmma::mma_sync(accB, al, Bf[k], accB);
                    } else {
                        wmma::mma_sync(acc[a], ah, Bf[k], acc[a]);
                        wmma::mma_sync(acc[a], al, Bf[k], acc[a]);
                    }
                }
            }
            if (MA == 1) {
#pragma unroll
                for (int i = 0; i < 8; i++) acc[0].x[i] += accB.x[i];
            }
#pragma unroll
            for (int a = 0; a < MA; a++)
                wmma::store_matrix_sync(sg + (a * 16) * TN + gate * 32 + hoff,
                                        acc[a], TN, wmma::mem_row_major);
            __syncthreads();
        }

        // ---- elementwise; c in registers ----
#pragma unroll
        for (int q = 0; q < CPT; q++) {
            const int e = threadIdx.x + q * 256;
            const int r = e / 32;
            const int h = e & 31;
            float pi, pf, pg, po;
            if (GPF) {
                pi = gp[q][0]; pf = gp[q][1]; pg = gp[q][2]; po = gp[q][3];
            } else {
                const size_t grow = (row0 + r) * 1024 + j0 + h;
                pi = G[grow + 0 * 256];
                pf = G[grow + 1 * 256];
                pg = G[grow + 2 * 256];
                po = G[grow + 3 * 256];
            }
            if (t) {
                pi += sg[r * TN + 0 * 32 + h];
                pf += sg[r * TN + 1 * 32 + h];
                pg += sg[r * TN + 2 * 32 + h];
                po += sg[r * TN + 3 * 32 + h];
            }
            const float cn = sigf(pf) * cst[q] + sigf(pi) * tanhf(pg);
            cst[q] = cn;
            Y[(row0 + r) * HD + j0 + h] = sigf(po) * tanhf(cn);
        }
        __syncthreads();
        if (threadIdx.x == 0) {
            __threadfence();
            atomicAdd(rdy + rm, 1u);
        }
    }
    // reset counter for next launch
    if (cg == 0 && threadIdx.x == 0) {
        const unsigned fin = (unsigned)C * (unsigned)STEPS;
        while (*(volatile unsigned*)(rdy + rm) < fin) __nanosleep(20);
        *(volatile unsigned*)(rdy + rm) = 0u;
        __threadfence();
    }
}

// ---------------- head: out = tanh((Y2+Y1) @ mlp_w^T + b) @ ad_w^T + ad_b ----
__global__ void __launch_bounds__(256, 2)
head_k(const float* __restrict__ Y2, const float* __restrict__ Y1,
       const float* __restrict__ mlpw, const float* __restrict__ mlpb,
       const float* __restrict__ adw, const float* __restrict__ adb,
       float* __restrict__ out) {
    __shared__ float sx[16][256];
    __shared__ float sh[16][256];
    __shared__ float so[16][48];

    const int warp = threadIdx.x >> 5;
    const size_t m0 = (size_t)blockIdx.x * 16;

    for (int e = threadIdx.x; e < 16 * 256; e += 256) {
        const size_t gi = m0 * 256 + e;
        sx[e / 256][e % 256] = Y2[gi] + Y1[gi];
    }
    __syncthreads();

    for (int st = warp; st < 16; st += 8) {
        FragC acc;
        wmma::fill_fragment(acc, 0.0f);
        kloop3(acc, &sx[0][0], 256, mlpw + (size_t)(st * 16) * 256, 256, 256);
        wmma::store_matrix_sync(&sh[0][st * 16], acc, 256, wmma::mem_row_major);
    }
    __syncthreads();
    for (int e = threadIdx.x; e < 16 * 256; e += 256)
        sh[e / 256][e % 256] = tanhf(sh[e / 256][e % 256] + mlpb[e % 256]);
    __syncthreads();

    if (warp < 3) {
        FragC acc;
        wmma::fill_fragment(acc, 0.0f);
        kloop3(acc, &sh[0][0], 256, adw + (size_t)(warp * 16) * 256, 256, 256);
        wmma::store_matrix_sync(&so[0][warp * 16], acc, 48, wmma::mem_row_major);
    }
    __syncthreads();
    for (int e = threadIdx.x; e < 16 * 48; e += 256)
        out[m0 * 48 + e] = so[e / 48][e % 48] + adb[e % 48];
}

// ---------------- host -------------------------------------------------------
extern "C" void kernel_launch(void* const* d_in, const int* in_sizes, int n_in,
                              void* d_out, int out_size) {
    const float* X     = (const float*)d_in[0];
    const float* Wih00 = (const float*)d_in[1];
    const float* Whh00 = (const float*)d_in[2];
    const float* bih00 = (const float*)d_in[3];
    const float* bhh00 = (const float*)d_in[4];
    const float* Wih01 = (const float*)d_in[5];
    const float* Whh01 = (const float*)d_in[6];
    const float* bih01 = (const float*)d_in[7];
    const float* bhh01 = (const float*)d_in[8];
    const float* Wih10 = (const float*)d_in[9];
    const float* Whh10 = (const float*)d_in[10];
    const float* bih10 = (const float*)d_in[11];
    const float* bhh10 = (const float*)d_in[12];
    const float* Wih11 = (const float*)d_in[13];
    const float* Whh11 = (const float*)d_in[14];
    const float* bih11 = (const float*)d_in[15];
    const float* bhh11 = (const float*)d_in[16];
    const float* mlpw  = (const float*)d_in[17];
    const float* mlpb  = (const float*)d_in[18];
    const float* adw   = (const float*)d_in[19];
    const float* adb   = (const float*)d_in[20];
    float* out = (float*)d_out;

    float *Xp, *Wih0p, *bRp, *Gp, *Yb;
    unsigned* rdyp;
    cudaGetSymbolAddress((void**)&Xp, g_Xp);
    cudaGetSymbolAddress((void**)&Wih0p, g_Wih0);
    cudaGetSymbolAddress((void**)&bRp, g_biasRep);
    cudaGetSymbolAddress((void**)&Gp, g_G);
    cudaGetSymbolAddress((void**)&Yb, g_Ybuf);
    cudaGetSymbolAddress((void**)&rdyp, g_rdy);
    float* Y0 = Yb;
    float* Y1 = Yb + (size_t)NRW * HD;
    float* Y2 = Yb + 2 * (size_t)NRW * HD;

    const int bsm = 4 * 128 * 36 * 4;   // 73.7 KB dynamic
    cudaFuncSetAttribute((const void*)bulk2_k<32>,
                         cudaFuncAttributeMaxDynamicSharedMemorySize, bsm);
    cudaFuncSetAttribute((const void*)bulk2_k<256>,
                         cudaFuncAttributeMaxDynamicSharedMemorySize, bsm);
    cudaFuncSetAttribute((const void*)seq_k<256, 256, 16, true>,
                         cudaFuncAttributeMaxDynamicSharedMemorySize, 16 * 128 * 4);
    cudaFuncSetAttribute((const void*)seq_k<128, 512, 32, true>,
                         cudaFuncAttributeMaxDynamicSharedMemorySize, 32 * 128 * 4);
    cudaFuncSetAttribute((const void*)seq_k<64, 1024, 64, false>,
                         cudaFuncAttributeMaxDynamicSharedMemorySize, 64 * 128 * 4);
    cudaFuncSetAttribute((const void*)seq_k<32, 2048, 128, false>,
                         cudaFuncAttributeMaxDynamicSharedMemorySize, 128 * 128 * 4);

    dim3 bgrid(8, 512);

    k_prep<<<512, 256>>>(X, Wih00, bih00, bhh00, bih01, bhh01,
                         bih10, bhh10, bih11, bhh11);                       // 1
    bulk2_k<32><<<bgrid, 256, bsm>>>(Xp, Wih0p, bRp + 0 * 16 * 1024, Gp);   // 2
    k_pad<<<1, 32>>>();                                                     // 3

    // 4 == profiled slot: seq L0
    seq_k<256, 256, 16, true><<<128, 256, 16 * 128 * 4>>>(Whh00, Gp, Y0, rdyp);

    bulk2_k<256><<<bgrid, 256, bsm>>>(Y0, Wih01, bRp + 1 * 16 * 1024, Gp);
    seq_k<128, 512, 32, true><<<128, 256, 32 * 128 * 4>>>(Whh01, Gp, Y1, rdyp);

    bulk2_k<256><<<bgrid, 256, bsm>>>(Y1, Wih10, bRp + 2 * 16 * 1024, Gp);
    seq_k<64, 1024, 64, false><<<128, 256, 64 * 128 * 4>>>(Whh10, Gp, Y0, rdyp);

    bulk2_k<256><<<bgrid, 256, bsm>>>(Y0, Wih11, bRp + 3 * 16 * 1024, Gp);
    seq_k<32, 2048, 128, false><<<128, 256, 128 * 128 * 4>>>(Whh11, Gp, Y2, rdyp);

    // head: (Y2 + Y1) -> tanh(mlp) -> adapter
    head_k<<<NRW / 16, 256>>>(Y2, Y1, mlpw, mlpb, adw, adb, out);
}

// round 13
// speedup vs baseline: 2.7026x; 1.1199x over previous
#include <cuda_runtime.h>
#include <mma.h>

using namespace nvcuda;

#define NRW 65536
#define HD  256

// ---------------- static device buffers --------------------------------------
__device__ __align__(256) float g_Xp[NRW * 32];             // padded input (cols 20..31 = 0)
__device__ __align__(256) float g_Wih0[1024 * 32];          // padded W_ih_00
__device__ __align__(256) float g_biasRep[4][16 * 1024];    // 16 replicated rows (b_ih+b_hh)
__device__ __align__(256) float g_G[(size_t)NRW * 1024];    // input preacts (+bias)
__device__ __align__(256) float g_Ybuf[3][(size_t)NRW * HD];
__device__ unsigned g_rdy[64];                              // per-row-group ready counters

typedef wmma::fragment<wmma::matrix_a, 16, 16, 8, wmma::precision::tf32, wmma::row_major> FragA;
typedef wmma::fragment<wmma::matrix_b, 16, 16, 8, wmma::precision::tf32, wmma::col_major> FragB;
typedef wmma::fragment<wmma::accumulator, 16, 16, 8, float> FragC;

__device__ __forceinline__ float sigf(float x) { return 1.0f / (1.0f + __expf(-x)); }

__device__ __forceinline__ void splitA(FragA& h, FragA& l) {
#pragma unroll
    for (int i = 0; i < h.num_elements; i++) {
        float v = h.x[i];
        float hh = wmma::__float_to_tf32(v);
        l.x[i] = wmma::__float_to_tf32(v - hh);
        h.x[i] = hh;
    }
}
__device__ __forceinline__ void splitB(FragB& h, FragB& l) {
#pragma unroll
    for (int i = 0; i < h.num_elements; i++) {
        float v = h.x[i];
        float hh = wmma::__float_to_tf32(v);
        l.x[i] = wmma::__float_to_tf32(v - hh);
        h.x[i] = hh;
    }
}
__device__ __forceinline__ void roundB(FragB& b) {
#pragma unroll
    for (int i = 0; i < b.num_elements; i++) b.x[i] = wmma::__float_to_tf32(b.x[i]);
}

// 3xTF32 K-loop (head kernel only)
__device__ __forceinline__ void kloop3(FragC& acc, const float* __restrict__ A, int lda,
                                       const float* __restrict__ B, int ldb, int K) {
    for (int k = 0; k < K; k += 8) {
        FragA ah, al;
        FragB bh, bl;
        wmma::load_matrix_sync(ah, A + k, lda);
        wmma::load_matrix_sync(bh, B + k, ldb);
        splitA(ah, al);
        splitB(bh, bl);
        wmma::mma_sync(acc, ah, bh, acc);
        wmma::mma_sync(acc, ah, bl, acc);
        wmma::mma_sync(acc, al, bh, acc);
    }
}

// ---------------- prep: pad X / W_ih_00, replicated bias rows ----------------
__global__ void k_prep(const float* __restrict__ x, const float* __restrict__ wih0,
                       const float* __restrict__ bi0, const float* __restrict__ bh0,
                       const float* __restrict__ bi1, const float* __restrict__ bh1,
                       const float* __restrict__ bi2, const float* __restrict__ bh2,
                       const float* __restrict__ bi3, const float* __restrict__ bh3) {
    int tid = blockIdx.x * blockDim.x + threadIdx.x;
    int nt = gridDim.x * blockDim.x;
    for (int i = tid; i < NRW * 20; i += nt)
        g_Xp[(size_t)(i / 20) * 32 + (i % 20)] = x[i];
    for (int i = tid; i < 1024 * 20; i += nt)
        g_Wih0[(i / 20) * 32 + (i % 20)] = wih0[i];
    for (int i = tid; i < 16 * 1024; i += nt) {
        int c = i % 1024;
        g_biasRep[0][i] = bi0[c] + bh0[c];
        g_biasRep[1][i] = bi1[c] + bh1[c];
        g_biasRep[2][i] = bi2[c] + bh2[c];
        g_biasRep[3][i] = bi3[c] + bh3[c];
    }
}

__global__ void k_pad() {}

// ---------------- bulk GEMM: cp.async double-buffered, BK=16, 2 blocks/SM ----
#define CPA16(dst, src) \
    asm volatile("cp.async.cg.shared.global [%0], [%1], 16;" :: "r"(dst), "l"(src))
#define CPA_COMMIT() asm volatile("cp.async.commit_group;" ::: "memory")
#define CPA_WAIT1()  asm volatile("cp.async.wait_group 1;" ::: "memory")
#define CPA_WAIT0()  asm volatile("cp.async.wait_group 0;" ::: "memory")

template <int K>
__global__ void __launch_bounds__(256, 2)
bulk2_k(const float* __restrict__ X, const float* __restrict__ W,
        const float* __restrict__ bR, float* __restrict__ G) {
    constexpr int NCH = K / 16;
    constexpr int LDS = 20;
    extern __shared__ float sm[];
    float* sA[2] = { sm, sm + 128 * LDS };
    float* sB[2] = { sm + 2 * 128 * LDS, sm + 3 * 128 * LDS };

    const int n0 = blockIdx.x * 128;
    const size_t m0 = (size_t)blockIdx.y * 128;
    const int w = threadIdx.x >> 5;
    const int wr = (w >> 1) * 32;
    const int wc = (w & 1) * 64;
    const int s0 = threadIdx.x * 2;

    auto issue = [&](int chunk, int buf) {
        const int k0 = chunk * 16;
#pragma unroll
        for (int j = 0; j < 2; j++) {
            const int s = s0 + j;
            const int r = s >> 2;
            const int c4 = (s & 3) * 4;
            CPA16((unsigned)__cvta_generic_to_shared(sA[buf] + r * LDS + c4),
                  X + (m0 + r) * K + k0 + c4);
            CPA16((unsigned)__cvta_generic_to_shared(sB[buf] + r * LDS + c4),
                  W + (size_t)(n0 + r) * K + k0 + c4);
        }
        CPA_COMMIT();
    };

    FragC acc[2][4];
#pragma unroll
    for (int a = 0; a < 2; a++)
#pragma unroll
        for (int b = 0; b < 4; b++) wmma::fill_fragment(acc[a][b], 0.0f);

    issue(0, 0);
    for (int c = 0; c < NCH; c++) {
        const int buf = c & 1;
        if (c + 1 < NCH) {
            issue(c + 1, buf ^ 1);
            CPA_WAIT1();
        } else {
            CPA_WAIT0();
        }
        __syncthreads();
#pragma unroll
        for (int kk = 0; kk < 16; kk += 8) {
            FragA ah[2], al[2];
#pragma unroll
            for (int a = 0; a < 2; a++) {
                wmma::load_matrix_sync(ah[a], sA[buf] + (wr + a * 16) * LDS + kk, LDS);
                splitA(ah[a], al[a]);
            }
#pragma unroll
            for (int b = 0; b < 4; b++) {
                FragB bh;
                wmma::load_matrix_sync(bh, sB[buf] + (wc + b * 16) * LDS + kk, LDS);
                roundB(bh);
#pragma unroll
                for (int a = 0; a < 2; a++) {
                    wmma::mma_sync(acc[a][b], ah[a], bh, acc[a][b]);
                    wmma::mma_sync(acc[a][b], al[a], bh, acc[a][b]);
                }
            }
        }
        __syncthreads();
    }
#pragma unroll
    for (int b = 0; b < 4; b++) {
        FragC bf;
        wmma::load_matrix_sync(bf, bR + n0 + wc + b * 16, 1024, wmma::mem_row_major);
#pragma unroll
        for (int a = 0; a < 2; a++) {
#pragma unroll
            for (int i = 0; i < bf.num_elements; i++) acc[a][b].x[i] += bf.x[i];
            wmma::store_matrix_sync(G + (m0 + wr + a * 16) * 1024 + n0 + wc + b * 16,
                                    acc[a][b], 1024, wmma::mem_row_major);
        }
    }
}

// ---------------- persistent sequential LSTM: reg-resident Whh + smem A -------
// TH=32: block owns TM rows x 32 hidden cols (128 gate cols). 8 warps, each
// owns one 16-col gate chunk (gate = w>>1, half = w&1) for ALL row tiles.
// B (Whh slice) = 32 fragments/warp, loaded + tf32-rounded ONCE per layer.
// Per step: A (h_{t-1}) staged into smem via one cp.async burst, then all
// warps read fragments from smem (no redundant global loads).
template <int STEPS, int BEFF, int TM, bool GPF>
__global__ void __launch_bounds__(256, 1)
seq_k(const float* __restrict__ Whh, const float* __restrict__ G,
      float* __restrict__ Y, unsigned* __restrict__ rdy) {
    constexpr int TN = 128;
    constexpr int C = 8;
    constexpr int MA = TM / 16;
    constexpr int CPT = TM * 32 / 256;
    constexpr int LDA = 260;
    constexpr bool DUAL = (MA <= 2);
    extern __shared__ float smem[];
    float* sA = smem;              // [TM][LDA] staged h_{t-1}
    float* sg = smem + TM * LDA;   // [TM][TN] gate tile exchange

    const int rm = blockIdx.x / C;
    const int cg = blockIdx.x % C;
    const int m0 = rm * TM;
    const int j0 = cg * 32;
    const int w = threadIdx.x >> 5;
    const int gate = w >> 1;
    const int hoff = (w & 1) * 16;

    // ---- load Whh fragments once (tf32-rounded) ----
    FragB Bf[32];
    {
        const float* Brow = Whh + (size_t)(gate * 256 + j0 + hoff) * HD;
#pragma unroll
        for (int k = 0; k < 32; k++) {
            wmma::load_matrix_sync(Bf[k], Brow + k * 8, HD);
            roundB(Bf[k]);
        }
    }

    float cst[CPT];
#pragma unroll
    for (int q = 0; q < CPT; q++) cst[q] = 0.0f;

    for (int t = 0; t < STEPS; t++) {
        const size_t row0 = (size_t)t * BEFF + m0;

        // optional register prefetch of G (pre-wait)
        float gp[GPF ? CPT : 1][4];
        if (GPF) {
#pragma unroll
            for (int q = 0; q < CPT; q++) {
                const int e = threadIdx.x + q * 256;
                const size_t grow = (row0 + e / 32) * 1024 + j0 + (e & 31);
#pragma unroll
                for (int g = 0; g < 4; g++) gp[q][g] = G[grow + g * 256];
            }
        }

        if (t) {
            if (threadIdx.x == 0) {
                const unsigned tgt = (unsigned)C * (unsigned)t;
                while (*(volatile unsigned*)(rdy + rm) < tgt) __nanosleep(20);
                __threadfence();
            }
            __syncthreads();

            // ---- stage A (h_{t-1}, TM x 256) into smem via cp.async burst ----
            {
                const float* Ab = Y + (row0 - BEFF) * HD;
#pragma unroll
                for (int idx = threadIdx.x; idx < TM * 64; idx += 256) {
                    const int r = idx >> 6;
                    const int c4 = (idx & 63) * 4;
                    CPA16((unsigned)__cvta_generic_to_shared(sA + r * LDA + c4),
                          Ab + (size_t)r * HD + c4);
                }
                CPA_COMMIT();
                CPA_WAIT0();
                __syncthreads();
            }

            FragC acc[MA];
            FragC accL[DUAL ? MA : 1];
#pragma unroll
            for (int a = 0; a < MA; a++) wmma::fill_fragment(acc[a], 0.0f);
            if (DUAL) {
#pragma unroll
                for (int a = 0; a < MA; a++) wmma::fill_fragment(accL[a], 0.0f);
            }

#pragma unroll
            for (int k = 0; k < 32; k++) {
#pragma unroll
                for (int a = 0; a < MA; a++) {
                    FragA ah, al;
                    wmma::load_matrix_sync(ah, sA + (a * 16) * LDA + k * 8, LDA);
                    splitA(ah, al);
                    wmma::mma_sync(acc[a], ah, Bf[k], acc[a]);
                    if (DUAL)
                        wmma::mma_sync(accL[a], al, Bf[k], accL[a]);
                    else
                        wmma::mma_sync(acc[a], al, Bf[k], acc[a]);
                }
            }
            if (DUAL) {
#pragma unroll
                for (int a = 0; a < MA; a++)
#pragma unroll
                    for (int i = 0; i < 8; i++) acc[a].x[i] += accL[a].x[i];
            }
            __syncthreads();   // sA reads done before sg overlap concerns (separate regions, but keep ordering cheap)
#pragma unroll
            for (int a = 0; a < MA; a++)
                wmma::store_matrix_sync(sg + (a * 16) * TN + gate * 32 + hoff,
                                        acc[a], TN, wmma::mem_row_major);
            __syncthreads();
        }

        // ---- elementwise; c in registers ----
#pragma unroll
        for (int q = 0; q < CPT; q++) {
            const int e = threadIdx.x + q * 256;
            const int r = e / 32;
            const int h = e & 31;
            float pi, pf, pg, po;
            if (GPF) {
                pi = gp[q][0]; pf = gp[q][1]; pg = gp[q][2]; po = gp[q][3];
            } else {
                const size_t grow = (row0 + r) * 1024 + j0 + h;
                pi = G[grow + 0 * 256];
                pf = G[grow + 1 * 256];
                pg = G[grow + 2 * 256];
                po = G[grow + 3 * 256];
            }
            if (t) {
                pi += sg[r * TN + 0 * 32 + h];
                pf += sg[r * TN + 1 * 32 + h];
                pg += sg[r * TN + 2 * 32 + h];
                po += sg[r * TN + 3 * 32 + h];
            }
            const float cn = sigf(pf) * cst[q] + sigf(pi) * tanhf(pg);
            cst[q] = cn;
            Y[(row0 + r) * HD + j0 + h] = sigf(po) * tanhf(cn);
        }
        __syncthreads();
        if (threadIdx.x == 0) {
            __threadfence();
            atomicAdd(rdy + rm, 1u);
        }
    }
    // reset counter for next launch
    if (cg == 0 && threadIdx.x == 0) {
        const unsigned fin = (unsigned)C * (unsigned)STEPS;
        while (*(volatile unsigned*)(rdy + rm) < fin) __nanosleep(20);
        *(volatile unsigned*)(rdy + rm) = 0u;
        __threadfence();
    }
}

// ---------------- head: out = tanh((Y2+Y1) @ mlp_w^T + b) @ ad_w^T + ad_b ----
__global__ void __launch_bounds__(256, 2)
head_k(const float* __restrict__ Y2, const float* __restrict__ Y1,
       const float* __restrict__ mlpw, const float* __restrict__ mlpb,
       const float* __restrict__ adw, const float* __restrict__ adb,
       float* __restrict__ out) {
    __shared__ float sx[16][256];
    __shared__ float sh[16][256];
    __shared__ float so[16][48];

    const int warp = threadIdx.x >> 5;
    const size_t m0 = (size_t)blockIdx.x * 16;

    for (int e = threadIdx.x; e < 16 * 256; e += 256) {
        const size_t gi = m0 * 256 + e;
        sx[e / 256][e % 256] = Y2[gi] + Y1[gi];
    }
    __syncthreads();

    for (int st = warp; st < 16; st += 8) {
        FragC acc;
        wmma::fill_fragment(acc, 0.0f);
        kloop3(acc, &sx[0][0], 256, mlpw + (size_t)(st * 16) * 256, 256, 256);
        wmma::store_matrix_sync(&sh[0][st * 16], acc, 256, wmma::mem_row_major);
    }
    __syncthreads();
    for (int e = threadIdx.x; e < 16 * 256; e += 256)
        sh[e / 256][e % 256] = tanhf(sh[e / 256][e % 256] + mlpb[e % 256]);
    __syncthreads();

    if (warp < 3) {
        FragC acc;
        wmma::fill_fragment(acc, 0.0f);
        kloop3(acc, &sh[0][0], 256, adw + (size_t)(warp * 16) * 256, 256, 256);
        wmma::store_matrix_sync(&so[0][warp * 16], acc, 48, wmma::mem_row_major);
    }
    __syncthreads();
    for (int e = threadIdx.x; e < 16 * 48; e += 256)
        out[m0 * 48 + e] = so[e / 48][e % 48] + adb[e % 48];
}

// ---------------- host -------------------------------------------------------
extern "C" void kernel_launch(void* const* d_in, const int* in_sizes, int n_in,
                              void* d_out, int out_size) {
    const float* X     = (const float*)d_in[0];
    const float* Wih00 = (const float*)d_in[1];
    const float* Whh00 = (const float*)d_in[2];
    const float* bih00 = (const float*)d_in[3];
    const float* bhh00 = (const float*)d_in[4];
    const float* Wih01 = (const float*)d_in[5];
    const float* Whh01 = (const float*)d_in[6];
    const float* bih01 = (const float*)d_in[7];
    const float* bhh01 = (const float*)d_in[8];
    const float* Wih10 = (const float*)d_in[9];
    const float* Whh10 = (const float*)d_in[10];
    const float* bih10 = (const float*)d_in[11];
    const float* bhh10 = (const float*)d_in[12];
    const float* Wih11 = (const float*)d_in[13];
    const float* Whh11 = (const float*)d_in[14];
    const float* bih11 = (const float*)d_in[15];
    const float* bhh11 = (const float*)d_in[16];
    const float* mlpw  = (const float*)d_in[17];
    const float* mlpb  = (const float*)d_in[18];
    const float* adw   = (const float*)d_in[19];
    const float* adb   = (const float*)d_in[20];
    float* out = (float*)d_out;

    float *Xp, *Wih0p, *bRp, *Gp, *Yb;
    unsigned* rdyp;
    cudaGetSymbolAddress((void**)&Xp, g_Xp);
    cudaGetSymbolAddress((void**)&Wih0p, g_Wih0);
    cudaGetSymbolAddress((void**)&bRp, g_biasRep);
    cudaGetSymbolAddress((void**)&Gp, g_G);
    cudaGetSymbolAddress((void**)&Yb, g_Ybuf);
    cudaGetSymbolAddress((void**)&rdyp, g_rdy);
    float* Y0 = Yb;
    float* Y1 = Yb + (size_t)NRW * HD;
    float* Y2 = Yb + 2 * (size_t)NRW * HD;

    const int bsm = 4 * 128 * 20 * 4;   // 41 KB dynamic -> 2 blocks/SM
    cudaFuncSetAttribute((const void*)bulk2_k<32>,
                         cudaFuncAttributeMaxDynamicSharedMemorySize, bsm);
    cudaFuncSetAttribute((const void*)bulk2_k<256>,
                         cudaFuncAttributeMaxDynamicSharedMemorySize, bsm);
    // seq smem: TM*260 (A stage) + TM*128 (gate tile) floats
    const int s16 = 16 * (260 + 128) * 4;
    const int s32 = 32 * (260 + 128) * 4;
    const int s64 = 64 * (260 + 128) * 4;
    const int s128 = 128 * (260 + 128) * 4;   // 198.7 KB
    cudaFuncSetAttribute((const void*)seq_k<256, 256, 16, true>,
                         cudaFuncAttributeMaxDynamicSharedMemorySize, s16);
    cudaFuncSetAttribute((const void*)seq_k<128, 512, 32, true>,
                         cudaFuncAttributeMaxDynamicSharedMemorySize, s32);
    cudaFuncSetAttribute((const void*)seq_k<64, 1024, 64, false>,
                         cudaFuncAttributeMaxDynamicSharedMemorySize, s64);
    cudaFuncSetAttribute((const void*)seq_k<32, 2048, 128, false>,
                         cudaFuncAttributeMaxDynamicSharedMemorySize, s128);

    dim3 bgrid(8, 512);

    k_prep<<<512, 256>>>(X, Wih00, bih00, bhh00, bih01, bhh01,
                         bih10, bhh10, bih11, bhh11);                       // 1
    bulk2_k<32><<<bgrid, 256, bsm>>>(Xp, Wih0p, bRp + 0 * 16 * 1024, Gp);   // 2
    k_pad<<<1, 32>>>();                                                     // 3

    // 4 == profiled slot: seq L0
    seq_k<256, 256, 16, true><<<128, 256, s16>>>(Whh00, Gp, Y0, rdyp);

    bulk2_k<256><<<bgrid, 256, bsm>>>(Y0, Wih01, bRp + 1 * 16 * 1024, Gp);
    seq_k<128, 512, 32, true><<<128, 256, s32>>>(Whh01, Gp, Y1, rdyp);

    bulk2_k<256><<<bgrid, 256, bsm>>>(Y1, Wih10, bRp + 2 * 16 * 1024, Gp);
    seq_k<64, 1024, 64, false><<<128, 256, s64>>>(Whh10, Gp, Y0, rdyp);

    bulk2_k<256><<<bgrid, 256, bsm>>>(Y0, Wih11, bRp + 3 * 16 * 1024, Gp);
    seq_k<32, 2048, 128, false><<<128, 256, s128>>>(Whh11, Gp, Y2, rdyp);

    // head: (Y2 + Y1) -> tanh(mlp) -> adapter
    head_k<<<NRW / 16, 256>>>(Y2, Y1, mlpw, mlpb, adw, adb, out);
}

// round 14
// speedup vs baseline: 2.7036x; 1.0004x over previous
#include <cuda_runtime.h>
#include <mma.h>

using namespace nvcuda;

#define NRW 65536
#define HD  256

// ---------------- static device buffers --------------------------------------
__device__ __align__(256) float g_Xp[NRW * 32];             // padded input (cols 20..31 = 0)
__device__ __align__(256) float g_Wih0[1024 * 32];          // padded W_ih_00
__device__ __align__(256) float g_biasRep[4][16 * 1024];    // 16 replicated rows (b_ih+b_hh)
__device__ __align__(256) float g_G[(size_t)NRW * 1024];    // input preacts (+bias)
__device__ __align__(256) float g_Ybuf[3][(size_t)NRW * HD];
__device__ unsigned g_rdy[64];                              // per-row-group ready counters

typedef wmma::fragment<wmma::matrix_a, 16, 16, 8, wmma::precision::tf32, wmma::row_major> FragA;
typedef wmma::fragment<wmma::matrix_b, 16, 16, 8, wmma::precision::tf32, wmma::col_major> FragB;
typedef wmma::fragment<wmma::accumulator, 16, 16, 8, float> FragC;

__device__ __forceinline__ float sigf(float x) { return 1.0f / (1.0f + __expf(-x)); }
// fast tanh via expf: (1 - e^-2x) / (1 + e^-2x); ~1e-6 error, ~5 instructions
__device__ __forceinline__ float tfast(float x) {
    const float e = __expf(-2.0f * x);
    return __fdividef(1.0f - e, 1.0f + e);
}

__device__ __forceinline__ void splitA(FragA& h, FragA& l) {
#pragma unroll
    for (int i = 0; i < h.num_elements; i++) {
        float v = h.x[i];
        float hh = wmma::__float_to_tf32(v);
        l.x[i] = wmma::__float_to_tf32(v - hh);
        h.x[i] = hh;
    }
}
__device__ __forceinline__ void splitB(FragB& h, FragB& l) {
#pragma unroll
    for (int i = 0; i < h.num_elements; i++) {
        float v = h.x[i];
        float hh = wmma::__float_to_tf32(v);
        l.x[i] = wmma::__float_to_tf32(v - hh);
        h.x[i] = hh;
    }
}
__device__ __forceinline__ void roundB(FragB& b) {
#pragma unroll
    for (int i = 0; i < b.num_elements; i++) b.x[i] = wmma::__float_to_tf32(b.x[i]);
}

// 3xTF32 K-loop (head kernel only)
__device__ __forceinline__ void kloop3(FragC& acc, const float* __restrict__ A, int lda,
                                       const float* __restrict__ B, int ldb, int K) {
    for (int k = 0; k < K; k += 8) {
        FragA ah, al;
        FragB bh, bl;
        wmma::load_matrix_sync(ah, A + k, lda);
        wmma::load_matrix_sync(bh, B + k, ldb);
        splitA(ah, al);
        splitB(bh, bl);
        wmma::mma_sync(acc, ah, bh, acc);
        wmma::mma_sync(acc, ah, bl, acc);
        wmma::mma_sync(acc, al, bh, acc);
    }
}

// ---------------- prep: pad X / W_ih_00, replicated bias rows ----------------
__global__ void k_prep(const float* __restrict__ x, const float* __restrict__ wih0,
                       const float* __restrict__ bi0, const float* __restrict__ bh0,
                       const float* __restrict__ bi1, const float* __restrict__ bh1,
                       const float* __restrict__ bi2, const float* __restrict__ bh2,
                       const float* __restrict__ bi3, const float* __restrict__ bh3) {
    int tid = blockIdx.x * blockDim.x + threadIdx.x;
    int nt = gridDim.x * blockDim.x;
    for (int i = tid; i < NRW * 20; i += nt)
        g_Xp[(size_t)(i / 20) * 32 + (i % 20)] = x[i];
    for (int i = tid; i < 1024 * 20; i += nt)
        g_Wih0[(i / 20) * 32 + (i % 20)] = wih0[i];
    for (int i = tid; i < 16 * 1024; i += nt) {
        int c = i % 1024;
        g_biasRep[0][i] = bi0[c] + bh0[c];
        g_biasRep[1][i] = bi1[c] + bh1[c];
        g_biasRep[2][i] = bi2[c] + bh2[c];
        g_biasRep[3][i] = bi3[c] + bh3[c];
    }
}

__global__ void k_pad() {}

// ---------------- bulk GEMM: cp.async double-buffered, BK=16, 2 blocks/SM ----
#define CPA16(dst, src) \
    asm volatile("cp.async.cg.shared.global [%0], [%1], 16;" :: "r"(dst), "l"(src))
#define CPA_COMMIT() asm volatile("cp.async.commit_group;" ::: "memory")
#define CPA_WAIT1()  asm volatile("cp.async.wait_group 1;" ::: "memory")
#define CPA_WAIT0()  asm volatile("cp.async.wait_group 0;" ::: "memory")

template <int K>
__global__ void __launch_bounds__(256, 2)
bulk2_k(const float* __restrict__ X, const float* __restrict__ W,
        const float* __restrict__ bR, float* __restrict__ G) {
    constexpr int NCH = K / 16;
    constexpr int LDS = 20;
    extern __shared__ float sm[];
    float* sA[2] = { sm, sm + 128 * LDS };
    float* sB[2] = { sm + 2 * 128 * LDS, sm + 3 * 128 * LDS };

    const int n0 = blockIdx.x * 128;
    const size_t m0 = (size_t)blockIdx.y * 128;
    const int w = threadIdx.x >> 5;
    const int wr = (w >> 1) * 32;
    const int wc = (w & 1) * 64;
    const int s0 = threadIdx.x * 2;

    auto issue = [&](int chunk, int buf) {
        const int k0 = chunk * 16;
#pragma unroll
        for (int j = 0; j < 2; j++) {
            const int s = s0 + j;
            const int r = s >> 2;
            const int c4 = (s & 3) * 4;
            CPA16((unsigned)__cvta_generic_to_shared(sA[buf] + r * LDS + c4),
                  X + (m0 + r) * K + k0 + c4);
            CPA16((unsigned)__cvta_generic_to_shared(sB[buf] + r * LDS + c4),
                  W + (size_t)(n0 + r) * K + k0 + c4);
        }
        CPA_COMMIT();
    };

    FragC acc[2][4];
#pragma unroll
    for (int a = 0; a < 2; a++)
#pragma unroll
        for (int b = 0; b < 4; b++) wmma::fill_fragment(acc[a][b], 0.0f);

    issue(0, 0);
    for (int c = 0; c < NCH; c++) {
        const int buf = c & 1;
        if (c + 1 < NCH) {
            issue(c + 1, buf ^ 1);
            CPA_WAIT1();
        } else {
            CPA_WAIT0();
        }
        __syncthreads();
#pragma unroll
        for (int kk = 0; kk < 16; kk += 8) {
            FragA ah[2], al[2];
#pragma unroll
            for (int a = 0; a < 2; a++) {
                wmma::load_matrix_sync(ah[a], sA[buf] + (wr + a * 16) * LDS + kk, LDS);
                splitA(ah[a], al[a]);
            }
#pragma unroll
            for (int b = 0; b < 4; b++) {
                FragB bh;
                wmma::load_matrix_sync(bh, sB[buf] + (wc + b * 16) * LDS + kk, LDS);
                roundB(bh);
#pragma unroll
                for (int a = 0; a < 2; a++) {
                    wmma::mma_sync(acc[a][b], ah[a], bh, acc[a][b]);
                    wmma::mma_sync(acc[a][b], al[a], bh, acc[a][b]);
                }
            }
        }
        __syncthreads();
    }
#pragma unroll
    for (int b = 0; b < 4; b++) {
        FragC bf;
        wmma::load_matrix_sync(bf, bR + n0 + wc + b * 16, 1024, wmma::mem_row_major);
#pragma unroll
        for (int a = 0; a < 2; a++) {
#pragma unroll
            for (int i = 0; i < bf.num_elements; i++) acc[a][b].x[i] += bf.x[i];
            wmma::store_matrix_sync(G + (m0 + wr + a * 16) * 1024 + n0 + wc + b * 16,
                                    acc[a][b], 1024, wmma::mem_row_major);
        }
    }
}

// ---------------- persistent sequential LSTM: reg-resident Whh + smem A -------
// TH=32: block owns TM rows x 32 hidden cols (128 gate cols). 8 warps, each
// owns one 16-col gate chunk (gate = w>>1, half = w&1) for ALL row tiles.
// B (Whh slice) = 32 fragments/warp, loaded + tf32-rounded ONCE per layer.
// Per step: A staged into smem via one cp.async burst; MA=1 uses 4 parallel
// accumulator chains (hi/lo x even/odd k) to cut the dependent-MMA depth.
template <int STEPS, int BEFF, int TM, bool GPF>
__global__ void __launch_bounds__(256, 1)
seq_k(const float* __restrict__ Whh, const float* __restrict__ G,
      float* __restrict__ Y, unsigned* __restrict__ rdy) {
    constexpr int TN = 128;
    constexpr int C = 8;
    constexpr int MA = TM / 16;
    constexpr int CPT = TM * 32 / 256;
    constexpr int LDA = 260;
    constexpr bool DUAL = (MA <= 2);
    constexpr bool QUAD = (MA == 1);
    extern __shared__ float smem[];
    float* sA = smem;              // [TM][LDA] staged h_{t-1}
    float* sg = smem + TM * LDA;   // [TM][TN] gate tile exchange

    const int rm = blockIdx.x / C;
    const int cg = blockIdx.x % C;
    const int m0 = rm * TM;
    const int j0 = cg * 32;
    const int w = threadIdx.x >> 5;
    const int gate = w >> 1;
    const int hoff = (w & 1) * 16;

    // ---- load Whh fragments once (tf32-rounded) ----
    FragB Bf[32];
    {
        const float* Brow = Whh + (size_t)(gate * 256 + j0 + hoff) * HD;
#pragma unroll
        for (int k = 0; k < 32; k++) {
            wmma::load_matrix_sync(Bf[k], Brow + k * 8, HD);
            roundB(Bf[k]);
        }
    }

    float cst[CPT];
#pragma unroll
    for (int q = 0; q < CPT; q++) cst[q] = 0.0f;

    for (int t = 0; t < STEPS; t++) {
        const size_t row0 = (size_t)t * BEFF + m0;

        // optional register prefetch of G (pre-wait)
        float gp[GPF ? CPT : 1][4];
        if (GPF) {
#pragma unroll
            for (int q = 0; q < CPT; q++) {
                const int e = threadIdx.x + q * 256;
                const size_t grow = (row0 + e / 32) * 1024 + j0 + (e & 31);
#pragma unroll
                for (int g = 0; g < 4; g++) gp[q][g] = G[grow + g * 256];
            }
        }

        if (t) {
            if (threadIdx.x == 0) {
                const unsigned tgt = (unsigned)C * (unsigned)t;
                while (*(volatile unsigned*)(rdy + rm) < tgt) __nanosleep(20);
                __threadfence();
            }
            __syncthreads();

            // ---- stage A (h_{t-1}, TM x 256) into smem via cp.async burst ----
            {
                const float* Ab = Y + (row0 - BEFF) * HD;
#pragma unroll
                for (int idx = threadIdx.x; idx < TM * 64; idx += 256) {
                    const int r = idx >> 6;
                    const int c4 = (idx & 63) * 4;
                    CPA16((unsigned)__cvta_generic_to_shared(sA + r * LDA + c4),
                          Ab + (size_t)r * HD + c4);
                }
                CPA_COMMIT();
                CPA_WAIT0();
                __syncthreads();
            }

            FragC acc[MA];
            FragC accL[DUAL ? MA : 1];
            FragC accQ0, accQ1;   // extra chains for MA==1
#pragma unroll
            for (int a = 0; a < MA; a++) wmma::fill_fragment(acc[a], 0.0f);
            if (DUAL) {
#pragma unroll
                for (int a = 0; a < MA; a++) wmma::fill_fragment(accL[a], 0.0f);
            }
            if (QUAD) {
                wmma::fill_fragment(accQ0, 0.0f);
                wmma::fill_fragment(accQ1, 0.0f);
            }

#pragma unroll
            for (int k = 0; k < 32; k++) {
#pragma unroll
                for (int a = 0; a < MA; a++) {
                    FragA ah, al;
                    wmma::load_matrix_sync(ah, sA + (a * 16) * LDA + k * 8, LDA);
                    splitA(ah, al);
                    if (QUAD && (k & 1)) {
                        wmma::mma_sync(accQ0, ah, Bf[k], accQ0);
                        wmma::mma_sync(accQ1, al, Bf[k], accQ1);
                    } else {
                        wmma::mma_sync(acc[a], ah, Bf[k], acc[a]);
                        if (DUAL)
                            wmma::mma_sync(accL[a], al, Bf[k], accL[a]);
                        else
                            wmma::mma_sync(acc[a], al, Bf[k], acc[a]);
                    }
                }
            }
            if (QUAD) {
#pragma unroll
                for (int i = 0; i < 8; i++)
                    acc[0].x[i] += accL[0].x[i] + accQ0.x[i] + accQ1.x[i];
            } else if (DUAL) {
#pragma unroll
                for (int a = 0; a < MA; a++)
#pragma unroll
                    for (int i = 0; i < 8; i++) acc[a].x[i] += accL[a].x[i];
            }
            // NOTE: no extra sync here — sA and sg are disjoint; all sA reads
            // complete before the post-elementwise barrier gates the next stage.
#pragma unroll
            for (int a = 0; a < MA; a++)
                wmma::store_matrix_sync(sg + (a * 16) * TN + gate * 32 + hoff,
                                        acc[a], TN, wmma::mem_row_major);
            __syncthreads();
        }

        // ---- elementwise; c in registers ----
#pragma unroll
        for (int q = 0; q < CPT; q++) {
            const int e = threadIdx.x + q * 256;
            const int r = e / 32;
            const int h = e & 31;
            float pi, pf, pg, po;
            if (GPF) {
                pi = gp[q][0]; pf = gp[q][1]; pg = gp[q][2]; po = gp[q][3];
            } else {
                const size_t grow = (row0 + r) * 1024 + j0 + h;
                pi = G[grow + 0 * 256];
                pf = G[grow + 1 * 256];
                pg = G[grow + 2 * 256];
                po = G[grow + 3 * 256];
            }
            if (t) {
                pi += sg[r * TN + 0 * 32 + h];
                pf += sg[r * TN + 1 * 32 + h];
                pg += sg[r * TN + 2 * 32 + h];
                po += sg[r * TN + 3 * 32 + h];
            }
            const float cn = sigf(pf) * cst[q] + sigf(pi) * tfast(pg);
            cst[q] = cn;
            Y[(row0 + r) * HD + j0 + h] = sigf(po) * tfast(cn);
        }
        __syncthreads();
        if (threadIdx.x == 0) {
            __threadfence();
            atomicAdd(rdy + rm, 1u);
        }
    }
    // reset counter for next launch
    if (cg == 0 && threadIdx.x == 0) {
        const unsigned fin = (unsigned)C * (unsigned)STEPS;
        while (*(volatile unsigned*)(rdy + rm) < fin) __nanosleep(20);
        *(volatile unsigned*)(rdy + rm) = 0u;
        __threadfence();
    }
}

// ---------------- head: out = tanh((Y2+Y1) @ mlp_w^T + b) @ ad_w^T + ad_b ----
__global__ void __launch_bounds__(256, 2)
head_k(const float* __restrict__ Y2, const float* __restrict__ Y1,
       const float* __restrict__ mlpw, const float* __restrict__ mlpb,
       const float* __restrict__ adw, const float* __restrict__ adb,
       float* __restrict__ out) {
    __shared__ float sx[16][256];
    __shared__ float sh[16][256];
    __shared__ float so[16][48];

    const int warp = threadIdx.x >> 5;
    const size_t m0 = (size_t)blockIdx.x * 16;

    for (int e = threadIdx.x; e < 16 * 256; e += 256) {
        const size_t gi = m0 * 256 + e;
        sx[e / 256][e % 256] = Y2[gi] + Y1[gi];
    }
    __syncthreads();

    for (int st = warp; st < 16; st += 8) {
        FragC acc;
        wmma::fill_fragment(acc, 0.0f);
        kloop3(acc, &sx[0][0], 256, mlpw + (size_t)(st * 16) * 256, 256, 256);
        wmma::store_matrix_sync(&sh[0][st * 16], acc, 256, wmma::mem_row_major);
    }
    __syncthreads();
    for (int e = threadIdx.x; e < 16 * 256; e += 256)
        sh[e / 256][e % 256] = tfast(sh[e / 256][e % 256] + mlpb[e % 256]);
    __syncthreads();

    if (warp < 3) {
        FragC acc;
        wmma::fill_fragment(acc, 0.0f);
        kloop3(acc, &sh[0][0], 256, adw + (size_t)(warp * 16) * 256, 256, 256);
        wmma::store_matrix_sync(&so[0][warp * 16], acc, 48, wmma::mem_row_major);
    }
    __syncthreads();
    for (int e = threadIdx.x; e < 16 * 48; e += 256)
        out[m0 * 48 + e] = so[e / 48][e % 48] + adb[e % 48];
}

// ---------------- host -------------------------------------------------------
extern "C" void kernel_launch(void* const* d_in, const int* in_sizes, int n_in,
                              void* d_out, int out_size) {
    const float* X     = (const float*)d_in[0];
    const float* Wih00 = (const float*)d_in[1];
    const float* Whh00 = (const float*)d_in[2];
    const float* bih00 = (const float*)d_in[3];
    const float* bhh00 = (const float*)d_in[4];
    const float* Wih01 = (const float*)d_in[5];
    const float* Whh01 = (const float*)d_in[6];
    const float* bih01 = (const float*)d_in[7];
    const float* bhh01 = (const float*)d_in[8];
    const float* Wih10 = (const float*)d_in[9];
    const float* Whh10 = (const float*)d_in[10];
    const float* bih10 = (const float*)d_in[11];
    const float* bhh10 = (const float*)d_in[12];
    const float* Wih11 = (const float*)d_in[13];
    const float* Whh11 = (const float*)d_in[14];
    const float* bih11 = (const float*)d_in[15];
    const float* bhh11 = (const float*)d_in[16];
    const float* mlpw  = (const float*)d_in[17];
    const float* mlpb  = (const float*)d_in[18];
    const float* adw   = (const float*)d_in[19];
    const float* adb   = (const float*)d_in[20];
    float* out = (float*)d_out;

    float *Xp, *Wih0p, *bRp, *Gp, *Yb;
    unsigned* rdyp;
    cudaGetSymbolAddress((void**)&Xp, g_Xp);
    cudaGetSymbolAddress((void**)&Wih0p, g_Wih0);
    cudaGetSymbolAddress((void**)&bRp, g_biasRep);
    cudaGetSymbolAddress((void**)&Gp, g_G);
    cudaGetSymbolAddress((void**)&Yb, g_Ybuf);
    cudaGetSymbolAddress((void**)&rdyp, g_rdy);
    float* Y0 = Yb;
    float* Y1 = Yb + (size_t)NRW * HD;
    float* Y2 = Yb + 2 * (size_t)NRW * HD;

    const int bsm = 4 * 128 * 20 * 4;   // 41 KB dynamic -> 2 blocks/SM
    cudaFuncSetAttribute((const void*)bulk2_k<32>,
                         cudaFuncAttributeMaxDynamicSharedMemorySize, bsm);
    cudaFuncSetAttribute((const void*)bulk2_k<256>,
                         cudaFuncAttributeMaxDynamicSharedMemorySize, bsm);
    // seq smem: TM*260 (A stage) + TM*128 (gate tile) floats
    const int s16 = 16 * (260 + 128) * 4;
    const int s32 = 32 * (260 + 128) * 4;
    const int s64 = 64 * (260 + 128) * 4;
    const int s128 = 128 * (260 + 128) * 4;   // 198.7 KB
    cudaFuncSetAttribute((const void*)seq_k<256, 256, 16, true>,
                         cudaFuncAttributeMaxDynamicSharedMemorySize, s16);
    cudaFuncSetAttribute((const void*)seq_k<128, 512, 32, true>,
                         cudaFuncAttributeMaxDynamicSharedMemorySize, s32);
    cudaFuncSetAttribute((const void*)seq_k<64, 1024, 64, false>,
                         cudaFuncAttributeMaxDynamicSharedMemorySize, s64);
    cudaFuncSetAttribute((const void*)seq_k<32, 2048, 128, false>,
                         cudaFuncAttributeMaxDynamicSharedMemorySize, s128);

    dim3 bgrid(8, 512);

    k_prep<<<512, 256>>>(X, Wih00, bih00, bhh00, bih01, bhh01,
                         bih10, bhh10, bih11, bhh11);                       // 1
    bulk2_k<32><<<bgrid, 256, bsm>>>(Xp, Wih0p, bRp + 0 * 16 * 1024, Gp);   // 2
    k_pad<<<1, 32>>>();                                                     // 3

    // 4 == profiled slot: seq L0
    seq_k<256, 256, 16, true><<<128, 256, s16>>>(Whh00, Gp, Y0, rdyp);

    bulk2_k<256><<<bgrid, 256, bsm>>>(Y0, Wih01, bRp + 1 * 16 * 1024, Gp);
    seq_k<128, 512, 32, true><<<128, 256, s32>>>(Whh01, Gp, Y1, rdyp);

    bulk2_k<256><<<bgrid, 256, bsm>>>(Y1, Wih10, bRp + 2 * 16 * 1024, Gp);
    seq_k<64, 1024, 64, false><<<128, 256, s64>>>(Whh10, Gp, Y0, rdyp);

    bulk2_k<256><<<bgrid, 256, bsm>>>(Y0, Wih11, bRp + 3 * 16 * 1024, Gp);
    seq_k<32, 2048, 128, false><<<128, 256, s128>>>(Whh11, Gp, Y2, rdyp);

    // head: (Y2 + Y1) -> tanh(mlp) -> adapter
    head_k<<<NRW / 16, 256>>>(Y2, Y1, mlpw, mlpb, adw, adb, out);
}